// round 1
// baseline (speedup 1.0000x reference)
#include <cuda_runtime.h>
#include <math.h>

// ---------------- problem constants ----------------
#define BATCH 16
#define HH 112
#define WW 112
#define SS 7
#define DD 3
#define HEADS 6
#define DIM 192
#define HIDDEN 768
#define NWIN 49                    // tokens per window
#define WIN_PER_IMG 256            // (112/7)^2
#define BW (BATCH * WIN_PER_IMG)   // 4096 windows
#define TOKENS (BW * NWIN)         // 200704
#define HEADDIM 32
#define LPIX (HH * WW)             // 12544

// ---------------- scratch (static device arrays; no allocation) ------------
__device__ float g_win[(size_t)TOKENS * DIM];    // LN1+gathered windows / reused for LN2 out
__device__ float g_q[(size_t)TOKENS * DIM];      // [Bw,h,N,d]
__device__ float g_k[(size_t)TOKENS * DIM];
__device__ float g_v[(size_t)TOKENS * DIM];
__device__ float g_att[(size_t)TOKENS * DIM];    // attention out, [token, C]
__device__ float g_x1[(size_t)TOKENS * DIM];     // x + attn branch (image layout)
__device__ float g_h[(size_t)TOKENS * HIDDEN];   // fc1 output

// ---------------- LayerNorm (one warp per token) ----------------
template <bool GATHER>
__global__ void ln_kernel(const float* __restrict__ x,
                          const float* __restrict__ gamma,
                          const float* __restrict__ beta,
                          float* __restrict__ out) {
    int warp = (blockIdx.x * blockDim.x + threadIdx.x) >> 5;
    int lane = threadIdx.x & 31;
    if (warp >= TOKENS) return;

    const float* src;
    if (GATHER) {
        // token (w, n) of shifted-window partition <- rolled image pixel
        int w = warp / NWIN, n = warp - w * NWIN;
        int b = w >> 8, ws = w & 255;
        int wh = ws >> 4, wc = ws & 15;
        int ii = n / SS, jj = n - ii * SS;
        int r = wh * SS + ii + DD; if (r >= HH) r -= HH;
        int c = wc * SS + jj + DD; if (c >= WW) c -= WW;
        src = x + ((size_t)b * LPIX + r * WW + c) * DIM;
    } else {
        src = x + (size_t)warp * DIM;
    }

    float v[6];
    float s = 0.f, s2 = 0.f;
#pragma unroll
    for (int k = 0; k < 6; k++) {
        v[k] = src[lane + 32 * k];
        s += v[k];
        s2 += v[k] * v[k];
    }
#pragma unroll
    for (int o = 16; o > 0; o >>= 1) {
        s  += __shfl_xor_sync(0xffffffffu, s, o);
        s2 += __shfl_xor_sync(0xffffffffu, s2, o);
    }
    float mu = s * (1.0f / DIM);
    float var = s2 * (1.0f / DIM) - mu * mu;
    float rstd = rsqrtf(var + 1e-5f);
    float* dst = out + (size_t)warp * DIM;
#pragma unroll
    for (int k = 0; k < 6; k++) {
        int cc = lane + 32 * k;
        dst[cc] = (v[k] - mu) * rstd * gamma[cc] + beta[cc];
    }
}

// ---------------- SGEMM: C[M,N] = A[M,K] @ W[N,K]^T + bias, fused epilogues -
// EPI 0: QKV split (q scaled, layout [Bw,h,N,d])
// EPI 1: proj -> window-merge + unshift + residual(x) -> x1 (image layout)
// EPI 2: exact GELU
// EPI 3: residual add (same layout) -> out
template <int EPI>
__global__ void __launch_bounds__(256)
sgemm_kernel(const float* __restrict__ A, const float* __restrict__ W,
             const float* __restrict__ bias,
             float* __restrict__ O0, float* __restrict__ O1, float* __restrict__ O2,
             const float* __restrict__ RES, int M, int N, int K) {
    const int BM = 128, BN = 64, BK = 16;
    __shared__ float As[BK][BM];
    __shared__ float Bs[BK][BN];

    int m0 = blockIdx.x * BM;
    int n0 = blockIdx.y * BN;
    int t = threadIdx.x;
    int tx = t & 15, ty = t >> 4;
    int row0 = ty * 8, col0 = tx * 4;

    float acc[8][4] = {};

    for (int k0 = 0; k0 < K; k0 += BK) {
        // A tile: 128x16 -> 512 float4, 2 per thread, stored transposed
#pragma unroll
        for (int sdx = 0; sdx < 2; sdx++) {
            int id = t + sdx * 256;
            int m = id >> 2, kq = id & 3;
            const float4 va = *(const float4*)&A[(size_t)(m0 + m) * K + k0 + kq * 4];
            As[kq * 4 + 0][m] = va.x;
            As[kq * 4 + 1][m] = va.y;
            As[kq * 4 + 2][m] = va.z;
            As[kq * 4 + 3][m] = va.w;
        }
        // W tile: 64x16 -> 256 float4, 1 per thread, stored transposed
        {
            int n = t >> 2, kq = t & 3;
            const float4 vb = *(const float4*)&W[(size_t)(n0 + n) * K + k0 + kq * 4];
            Bs[kq * 4 + 0][n] = vb.x;
            Bs[kq * 4 + 1][n] = vb.y;
            Bs[kq * 4 + 2][n] = vb.z;
            Bs[kq * 4 + 3][n] = vb.w;
        }
        __syncthreads();
#pragma unroll
        for (int kk = 0; kk < BK; kk++) {
            float a[8], b[4];
            *(float4*)&a[0] = *(const float4*)&As[kk][row0];
            *(float4*)&a[4] = *(const float4*)&As[kk][row0 + 4];
            *(float4*)&b[0] = *(const float4*)&Bs[kk][col0];
#pragma unroll
            for (int i = 0; i < 8; i++)
#pragma unroll
                for (int j = 0; j < 4; j++)
                    acc[i][j] += a[i] * b[j];
        }
        __syncthreads();
    }

#pragma unroll
    for (int i = 0; i < 8; i++) {
        int r = m0 + row0 + i;
#pragma unroll
        for (int j = 0; j < 4; j++) {
            int c = n0 + col0 + j;
            float val = acc[i][j] + bias[c];
            if (EPI == 0) {
                int which = c / DIM;
                int c2 = c - which * DIM;
                int hd = c2 >> 5, dd = c2 & 31;
                int w = r / NWIN, n = r - w * NWIN;
                size_t off = ((size_t)(w * HEADS + hd) * NWIN + n) * HEADDIM + dd;
                if (which == 0)      O0[off] = val * 0.17677669529663687f; // d^-0.5
                else if (which == 1) O1[off] = val;
                else                 O2[off] = val;
            } else if (EPI == 1) {
                int w = r / NWIN, n = r - w * NWIN;
                int b = w >> 8, ws = w & 255;
                int wh = ws >> 4, wc = ws & 15;
                int ii = n / SS, jj = n - ii * SS;
                int rr = wh * SS + ii + DD; if (rr >= HH) rr -= HH;
                int cc = wc * SS + jj + DD; if (cc >= WW) cc -= WW;
                size_t dst = ((size_t)b * LPIX + rr * WW + cc) * DIM + c;
                O0[dst] = val + RES[dst];
            } else if (EPI == 2) {
                size_t idx = (size_t)r * N + c;
                O0[idx] = 0.5f * val * (1.0f + erff(val * 0.70710678118654752f));
            } else {
                size_t idx = (size_t)r * N + c;
                O0[idx] = val + RES[idx];
            }
        }
    }
}

// ---------------- fused window attention: one block per (window, head) -----
__global__ void __launch_bounds__(256)
attn_kernel(const float* __restrict__ q, const float* __restrict__ k,
            const float* __restrict__ v, const float* __restrict__ rpe,
            float* __restrict__ out) {
    int bh = blockIdx.x;
    int w = bh / HEADS, h = bh - w * HEADS;

    __shared__ float qs[NWIN * HEADDIM];
    __shared__ float ks[NWIN * HEADDIM];
    __shared__ float vs[NWIN * HEADDIM];
    __shared__ float sc[NWIN * NWIN];
    __shared__ int lbl[NWIN];

    const float* qp = q + (size_t)bh * NWIN * HEADDIM;
    const float* kp = k + (size_t)bh * NWIN * HEADDIM;
    const float* vp = v + (size_t)bh * NWIN * HEADDIM;
    int t = threadIdx.x;

    for (int i = t; i < NWIN * HEADDIM; i += 256) {
        qs[i] = qp[i];
        ks[i] = kp[i];
        vs[i] = vp[i];
    }
    if (t < NWIN) {
        // shift-region labels on the (unrolled) label image
        int ws = w & 255;
        int wh = ws >> 4, wc = ws & 15;
        int ii = t / SS, jj = t - ii * SS;
        int r = wh * SS + ii, c = wc * SS + jj;
        int rb = r < (HH - SS) ? 0 : (r < (HH - DD) ? 1 : 2);
        int cb = c < (WW - SS) ? 0 : (c < (WW - DD) ? 1 : 2);
        const int LT[9] = {0, 5, 4, 7, 8, 6, 2, 3, 1};
        lbl[t] = LT[rb * 3 + cb];
    }
    __syncthreads();

    for (int idx = t; idx < NWIN * NWIN; idx += 256) {
        int n = idx / NWIN, m = idx - n * NWIN;
        float s = 0.f;
#pragma unroll
        for (int kk = 0; kk < HEADDIM; kk++)
            s += qs[n * HEADDIM + kk] * ks[m * HEADDIM + kk];
        int di = n / SS - m / SS + (SS - 1);
        int dj = n % SS - m % SS + (SS - 1);
        s += rpe[(di * (2 * SS - 1) + dj) * HEADS + h];
        if (lbl[n] != lbl[m]) s -= 100.0f;
        sc[idx] = s;
    }
    __syncthreads();

    int wid = t >> 5, lane = t & 31;
    for (int row = wid; row < NWIN; row += 8) {
        float mx = -1e30f;
        for (int m = lane; m < NWIN; m += 32) mx = fmaxf(mx, sc[row * NWIN + m]);
#pragma unroll
        for (int o = 16; o > 0; o >>= 1) mx = fmaxf(mx, __shfl_xor_sync(0xffffffffu, mx, o));
        float sum = 0.f;
        for (int m = lane; m < NWIN; m += 32) {
            float e = expf(sc[row * NWIN + m] - mx);
            sc[row * NWIN + m] = e;
            sum += e;
        }
#pragma unroll
        for (int o = 16; o > 0; o >>= 1) sum += __shfl_xor_sync(0xffffffffu, sum, o);
        float inv = 1.0f / sum;
        for (int m = lane; m < NWIN; m += 32) sc[row * NWIN + m] *= inv;
    }
    __syncthreads();

    for (int idx = t; idx < NWIN * HEADDIM; idx += 256) {
        int n = idx >> 5, dd = idx & 31;
        float accv = 0.f;
#pragma unroll
        for (int m = 0; m < NWIN; m++)
            accv += sc[n * NWIN + m] * vs[m * HEADDIM + dd];
        out[((size_t)w * NWIN + n) * DIM + h * HEADDIM + dd] = accv;
    }
}

// ---------------- launcher ----------------
extern "C" void kernel_launch(void* const* d_in, const int* in_sizes, int n_in,
                              void* d_out, int out_size) {
    const float* x        = (const float*)d_in[0];
    const float* w_qkv    = (const float*)d_in[1];
    const float* b_qkv    = (const float*)d_in[2];
    const float* w_proj   = (const float*)d_in[3];
    const float* b_proj   = (const float*)d_in[4];
    const float* rpe      = (const float*)d_in[5];
    const float* gamma1   = (const float*)d_in[6];
    const float* beta1    = (const float*)d_in[7];
    const float* gamma2   = (const float*)d_in[8];
    const float* beta2    = (const float*)d_in[9];
    const float* w_fc1    = (const float*)d_in[10];
    const float* b_fc1    = (const float*)d_in[11];
    const float* w_fc2    = (const float*)d_in[12];
    const float* b_fc2    = (const float*)d_in[13];
    float* out = (float*)d_out;

    float *win, *q, *k, *v, *att, *x1, *hbuf;
    cudaGetSymbolAddress((void**)&win,  g_win);
    cudaGetSymbolAddress((void**)&q,    g_q);
    cudaGetSymbolAddress((void**)&k,    g_k);
    cudaGetSymbolAddress((void**)&v,    g_v);
    cudaGetSymbolAddress((void**)&att,  g_att);
    cudaGetSymbolAddress((void**)&x1,   g_x1);
    cudaGetSymbolAddress((void**)&hbuf, g_h);

    const int LN_BLOCKS = TOKENS / 8; // 8 warps/block, 1 warp/token

    // 1) LN1 + shift + window gather
    ln_kernel<true><<<LN_BLOCKS, 256>>>(x, gamma1, beta1, win);

    // 2) QKV GEMM (M=200704, N=576, K=192), split epilogue
    sgemm_kernel<0><<<dim3(TOKENS / 128, 576 / 64), 256>>>(
        win, w_qkv, b_qkv, q, k, v, nullptr, TOKENS, 3 * DIM, DIM);

    // 3) fused windowed attention
    attn_kernel<<<BW * HEADS, 256>>>(q, k, v, rpe, att);

    // 4) proj GEMM + merge/unshift + residual -> x1
    sgemm_kernel<1><<<dim3(TOKENS / 128, DIM / 64), 256>>>(
        att, w_proj, b_proj, x1, nullptr, nullptr, x, TOKENS, DIM, DIM);

    // 5) LN2 (x1 -> win reused as buffer)
    ln_kernel<false><<<LN_BLOCKS, 256>>>(x1, gamma2, beta2, win);

    // 6) fc1 GEMM + GELU (M, N=768, K=192)
    sgemm_kernel<2><<<dim3(TOKENS / 128, HIDDEN / 64), 256>>>(
        win, w_fc1, b_fc1, hbuf, nullptr, nullptr, nullptr, TOKENS, HIDDEN, DIM);

    // 7) fc2 GEMM + residual(x1) -> d_out (M, N=192, K=768)
    sgemm_kernel<3><<<dim3(TOKENS / 128, DIM / 64), 256>>>(
        hbuf, w_fc2, b_fc2, out, nullptr, nullptr, x1, TOKENS, DIM, HIDDEN);
}

// round 2
// speedup vs baseline: 1.3655x; 1.3655x over previous
#include <cuda_runtime.h>
#include <math.h>

// ---------------- problem constants ----------------
#define BATCH 16
#define HH 112
#define WW 112
#define SS 7
#define DD 3
#define HEADS 6
#define DIM 192
#define HIDDEN 768
#define NWIN 49                    // tokens per window
#define WIN_PER_IMG 256            // (112/7)^2
#define BW (BATCH * WIN_PER_IMG)   // 4096 windows
#define TOKENS (BW * NWIN)         // 200704
#define HEADDIM 32
#define LPIX (HH * WW)             // 12544

// ---------------- scratch (static device arrays; no allocation) ------------
__device__ float g_win[(size_t)TOKENS * DIM];
__device__ float g_q[(size_t)TOKENS * DIM];
__device__ float g_k[(size_t)TOKENS * DIM];
__device__ float g_v[(size_t)TOKENS * DIM];
__device__ float g_att[(size_t)TOKENS * DIM];
__device__ float g_x1[(size_t)TOKENS * DIM];
__device__ float g_h[(size_t)TOKENS * HIDDEN];

// ---------------- helpers ----------------
__device__ __forceinline__ unsigned f2tf32(float x) {
    unsigned r;
    asm("cvt.rna.tf32.f32 %0, %1;" : "=r"(r) : "f"(x));
    return r;
}

__device__ __forceinline__ void mma_tf32(float* d, const unsigned* a, const unsigned* b) {
    asm volatile(
        "mma.sync.aligned.m16n8k8.row.col.f32.tf32.tf32.f32 "
        "{%0,%1,%2,%3}, {%4,%5,%6,%7}, {%8,%9}, {%0,%1,%2,%3};"
        : "+f"(d[0]), "+f"(d[1]), "+f"(d[2]), "+f"(d[3])
        : "r"(a[0]), "r"(a[1]), "r"(a[2]), "r"(a[3]), "r"(b[0]), "r"(b[1]));
}

// ---------------- LayerNorm (one warp per token) ----------------
template <bool GATHER>
__global__ void ln_kernel(const float* __restrict__ x,
                          const float* __restrict__ gamma,
                          const float* __restrict__ beta,
                          float* __restrict__ out) {
    int warp = (blockIdx.x * blockDim.x + threadIdx.x) >> 5;
    int lane = threadIdx.x & 31;
    if (warp >= TOKENS) return;

    const float* src;
    if (GATHER) {
        int w = warp / NWIN, n = warp - w * NWIN;
        int b = w >> 8, ws = w & 255;
        int wh = ws >> 4, wc = ws & 15;
        int ii = n / SS, jj = n - ii * SS;
        int r = wh * SS + ii + DD; if (r >= HH) r -= HH;
        int c = wc * SS + jj + DD; if (c >= WW) c -= WW;
        src = x + ((size_t)b * LPIX + r * WW + c) * DIM;
    } else {
        src = x + (size_t)warp * DIM;
    }

    float v[6];
    float s = 0.f, s2 = 0.f;
#pragma unroll
    for (int k = 0; k < 6; k++) {
        v[k] = src[lane + 32 * k];
        s += v[k];
        s2 += v[k] * v[k];
    }
#pragma unroll
    for (int o = 16; o > 0; o >>= 1) {
        s  += __shfl_xor_sync(0xffffffffu, s, o);
        s2 += __shfl_xor_sync(0xffffffffu, s2, o);
    }
    float mu = s * (1.0f / DIM);
    float var = s2 * (1.0f / DIM) - mu * mu;
    float rstd = rsqrtf(var + 1e-5f);
    float* dst = out + (size_t)warp * DIM;
#pragma unroll
    for (int k = 0; k < 6; k++) {
        int cc = lane + 32 * k;
        dst[cc] = (v[k] - mu) * rstd * gamma[cc] + beta[cc];
    }
}

// ---------------- tf32 tensor-core GEMM: C = A[M,K] @ W[N,K]^T + bias ------
// Block tile 256x64x32, 8 warps (4 m x 2 n), warp tile 64x32.
// EPI 0: QKV split (q scaled, layout [Bw,h,N,d])
// EPI 1: proj -> window-merge + unshift + residual(x)
// EPI 2: exact GELU
// EPI 3: residual add
#define BM 256
#define BN 64
#define BK 32
#define AS_STRIDE 264   // BM + 8  -> A-frag banks (8q+g) all distinct
#define BS_STRIDE 36    // BK + 4  -> B-frag banks (4g+q) all distinct

template <int EPI>
__global__ void __launch_bounds__(256, 2)
gemm_tf32(const float* __restrict__ A, const float* __restrict__ W,
          const float* __restrict__ bias,
          float* __restrict__ O0, float* __restrict__ O1, float* __restrict__ O2,
          const float* __restrict__ RES, int M, int N, int K) {
    __shared__ unsigned As[BK * AS_STRIDE];   // [k][m] (transposed)
    __shared__ unsigned Bs[BN * BS_STRIDE];   // [n][k]

    const int t = threadIdx.x;
    const int wid = t >> 5, lane = t & 31;
    const int g = lane >> 2, q = lane & 3;
    const int warp_m = wid & 3;     // 4 warps along M
    const int warp_n = wid >> 2;    // 2 warps along N
    const int m0 = blockIdx.x * BM;
    const int n0 = blockIdx.y * BN;

    float acc[4][4][4] = {};        // [mfrag][nfrag][reg]

    for (int k0 = 0; k0 < K; k0 += BK) {
        // ---- load A tile (256x32) transposed, tf32-converted: 8 float4/thread
#pragma unroll
        for (int i = 0; i < 8; i++) {
            int id = i * 256 + t;
            int m = id >> 3, kq = (id & 7) * 4;
            const float4 va = *(const float4*)&A[(size_t)(m0 + m) * K + k0 + kq];
            As[(kq + 0) * AS_STRIDE + m] = f2tf32(va.x);
            As[(kq + 1) * AS_STRIDE + m] = f2tf32(va.y);
            As[(kq + 2) * AS_STRIDE + m] = f2tf32(va.z);
            As[(kq + 3) * AS_STRIDE + m] = f2tf32(va.w);
        }
        // ---- load B tile (64x32) n-major, tf32-converted: 2 float4/thread
#pragma unroll
        for (int i = 0; i < 2; i++) {
            int id = i * 256 + t;
            int n = id >> 3, kq = (id & 7) * 4;
            const float4 vb = *(const float4*)&W[(size_t)(n0 + n) * K + k0 + kq];
            uint4 u;
            u.x = f2tf32(vb.x); u.y = f2tf32(vb.y);
            u.z = f2tf32(vb.z); u.w = f2tf32(vb.w);
            *(uint4*)&Bs[n * BS_STRIDE + kq] = u;
        }
        __syncthreads();

#pragma unroll
        for (int ks = 0; ks < 4; ks++) {
            unsigned a[4][4], b[4][2];
            const int krow0 = (ks * 8 + q) * AS_STRIDE;
            const int krow1 = (ks * 8 + q + 4) * AS_STRIDE;
#pragma unroll
            for (int mf = 0; mf < 4; mf++) {
                int row = warp_m * 64 + mf * 16 + g;
                a[mf][0] = As[krow0 + row];
                a[mf][1] = As[krow0 + row + 8];
                a[mf][2] = As[krow1 + row];
                a[mf][3] = As[krow1 + row + 8];
            }
#pragma unroll
            for (int nf = 0; nf < 4; nf++) {
                int col = (warp_n * 32 + nf * 8 + g) * BS_STRIDE + ks * 8;
                b[nf][0] = Bs[col + q];
                b[nf][1] = Bs[col + q + 4];
            }
#pragma unroll
            for (int mf = 0; mf < 4; mf++)
#pragma unroll
                for (int nf = 0; nf < 4; nf++)
                    mma_tf32(acc[mf][nf], a[mf], b[nf]);
        }
        __syncthreads();
    }

    // ---- epilogue ----
#pragma unroll
    for (int mf = 0; mf < 4; mf++) {
#pragma unroll
        for (int nf = 0; nf < 4; nf++) {
#pragma unroll
            for (int e = 0; e < 4; e++) {
                int r = m0 + warp_m * 64 + mf * 16 + g + ((e >> 1) ? 8 : 0);
                int c = n0 + warp_n * 32 + nf * 8 + 2 * q + (e & 1);
                float val = acc[mf][nf][e] + bias[c];
                if (EPI == 0) {
                    int which = c / DIM;
                    int c2 = c - which * DIM;
                    int hd = c2 >> 5, dd = c2 & 31;
                    int w = r / NWIN, n = r - w * NWIN;
                    size_t off = ((size_t)(w * HEADS + hd) * NWIN + n) * HEADDIM + dd;
                    if (which == 0)      O0[off] = val * 0.17677669529663687f;
                    else if (which == 1) O1[off] = val;
                    else                 O2[off] = val;
                } else if (EPI == 1) {
                    int w = r / NWIN, n = r - w * NWIN;
                    int b = w >> 8, ws = w & 255;
                    int wh = ws >> 4, wc = ws & 15;
                    int ii = n / SS, jj = n - ii * SS;
                    int rr = wh * SS + ii + DD; if (rr >= HH) rr -= HH;
                    int cc = wc * SS + jj + DD; if (cc >= WW) cc -= WW;
                    size_t dst = ((size_t)b * LPIX + rr * WW + cc) * DIM + c;
                    O0[dst] = val + RES[dst];
                } else if (EPI == 2) {
                    size_t idx = (size_t)r * N + c;
                    O0[idx] = 0.5f * val * (1.0f + erff(val * 0.70710678118654752f));
                } else {
                    size_t idx = (size_t)r * N + c;
                    O0[idx] = val + RES[idx];
                }
            }
        }
    }
}

// ---------------- fused window attention: one block per (window, head) -----
__global__ void __launch_bounds__(256)
attn_kernel(const float* __restrict__ q, const float* __restrict__ k,
            const float* __restrict__ v, const float* __restrict__ rpe,
            float* __restrict__ out) {
    int bh = blockIdx.x;
    int w = bh / HEADS, h = bh - w * HEADS;

    __shared__ float qs[NWIN * HEADDIM];
    __shared__ float ks[NWIN * HEADDIM];
    __shared__ float vs[NWIN * HEADDIM];
    __shared__ float sc[NWIN * NWIN];
    __shared__ int lbl[NWIN];

    const float* qp = q + (size_t)bh * NWIN * HEADDIM;
    const float* kp = k + (size_t)bh * NWIN * HEADDIM;
    const float* vp = v + (size_t)bh * NWIN * HEADDIM;
    int t = threadIdx.x;

    for (int i = t; i < NWIN * HEADDIM; i += 256) {
        qs[i] = qp[i];
        ks[i] = kp[i];
        vs[i] = vp[i];
    }
    if (t < NWIN) {
        int ws = w & 255;
        int wh = ws >> 4, wc = ws & 15;
        int ii = t / SS, jj = t - ii * SS;
        int r = wh * SS + ii, c = wc * SS + jj;
        int rb = r < (HH - SS) ? 0 : (r < (HH - DD) ? 1 : 2);
        int cb = c < (WW - SS) ? 0 : (c < (WW - DD) ? 1 : 2);
        const int LT[9] = {0, 5, 4, 7, 8, 6, 2, 3, 1};
        lbl[t] = LT[rb * 3 + cb];
    }
    __syncthreads();

    for (int idx = t; idx < NWIN * NWIN; idx += 256) {
        int n = idx / NWIN, m = idx - n * NWIN;
        float s = 0.f;
#pragma unroll
        for (int kk = 0; kk < HEADDIM; kk++)
            s += qs[n * HEADDIM + kk] * ks[m * HEADDIM + kk];
        int di = n / SS - m / SS + (SS - 1);
        int dj = n % SS - m % SS + (SS - 1);
        s += rpe[(di * (2 * SS - 1) + dj) * HEADS + h];
        if (lbl[n] != lbl[m]) s -= 100.0f;
        sc[idx] = s;
    }
    __syncthreads();

    int wid = t >> 5, lane = t & 31;
    for (int row = wid; row < NWIN; row += 8) {
        float mx = -1e30f;
        for (int m = lane; m < NWIN; m += 32) mx = fmaxf(mx, sc[row * NWIN + m]);
#pragma unroll
        for (int o = 16; o > 0; o >>= 1) mx = fmaxf(mx, __shfl_xor_sync(0xffffffffu, mx, o));
        float sum = 0.f;
        for (int m = lane; m < NWIN; m += 32) {
            float e = expf(sc[row * NWIN + m] - mx);
            sc[row * NWIN + m] = e;
            sum += e;
        }
#pragma unroll
        for (int o = 16; o > 0; o >>= 1) sum += __shfl_xor_sync(0xffffffffu, sum, o);
        float inv = 1.0f / sum;
        for (int m = lane; m < NWIN; m += 32) sc[row * NWIN + m] *= inv;
    }
    __syncthreads();

    for (int idx = t; idx < NWIN * HEADDIM; idx += 256) {
        int n = idx >> 5, dd = idx & 31;
        float accv = 0.f;
#pragma unroll
        for (int m = 0; m < NWIN; m++)
            accv += sc[n * NWIN + m] * vs[m * HEADDIM + dd];
        out[((size_t)w * NWIN + n) * DIM + h * HEADDIM + dd] = accv;
    }
}

// ---------------- launcher ----------------
extern "C" void kernel_launch(void* const* d_in, const int* in_sizes, int n_in,
                              void* d_out, int out_size) {
    const float* x        = (const float*)d_in[0];
    const float* w_qkv    = (const float*)d_in[1];
    const float* b_qkv    = (const float*)d_in[2];
    const float* w_proj   = (const float*)d_in[3];
    const float* b_proj   = (const float*)d_in[4];
    const float* rpe      = (const float*)d_in[5];
    const float* gamma1   = (const float*)d_in[6];
    const float* beta1    = (const float*)d_in[7];
    const float* gamma2   = (const float*)d_in[8];
    const float* beta2    = (const float*)d_in[9];
    const float* w_fc1    = (const float*)d_in[10];
    const float* b_fc1    = (const float*)d_in[11];
    const float* w_fc2    = (const float*)d_in[12];
    const float* b_fc2    = (const float*)d_in[13];
    float* out = (float*)d_out;

    float *win, *q, *k, *v, *att, *x1, *hbuf;
    cudaGetSymbolAddress((void**)&win,  g_win);
    cudaGetSymbolAddress((void**)&q,    g_q);
    cudaGetSymbolAddress((void**)&k,    g_k);
    cudaGetSymbolAddress((void**)&v,    g_v);
    cudaGetSymbolAddress((void**)&att,  g_att);
    cudaGetSymbolAddress((void**)&x1,   g_x1);
    cudaGetSymbolAddress((void**)&hbuf, g_h);

    const int LN_BLOCKS = TOKENS / 8;
    const int GX = TOKENS / BM;   // 784

    // 1) LN1 + shift + window gather
    ln_kernel<true><<<LN_BLOCKS, 256>>>(x, gamma1, beta1, win);

    // 2) QKV GEMM (N=576)
    gemm_tf32<0><<<dim3(GX, 576 / BN), 256>>>(
        win, w_qkv, b_qkv, q, k, v, nullptr, TOKENS, 3 * DIM, DIM);

    // 3) fused windowed attention
    attn_kernel<<<BW * HEADS, 256>>>(q, k, v, rpe, att);

    // 4) proj GEMM + merge/unshift + residual -> x1
    gemm_tf32<1><<<dim3(GX, DIM / BN), 256>>>(
        att, w_proj, b_proj, x1, nullptr, nullptr, x, TOKENS, DIM, DIM);

    // 5) LN2
    ln_kernel<false><<<LN_BLOCKS, 256>>>(x1, gamma2, beta2, win);

    // 6) fc1 GEMM + GELU (N=768)
    gemm_tf32<2><<<dim3(GX, HIDDEN / BN), 256>>>(
        win, w_fc1, b_fc1, hbuf, nullptr, nullptr, nullptr, TOKENS, HIDDEN, DIM);

    // 7) fc2 GEMM + residual(x1) -> d_out (N=192, K=768)
    gemm_tf32<3><<<dim3(GX, DIM / BN), 256>>>(
        hbuf, w_fc2, b_fc2, out, nullptr, nullptr, x1, TOKENS, DIM, HIDDEN);
}

// round 3
// speedup vs baseline: 3.3711x; 2.4689x over previous
#include <cuda_runtime.h>
#include <cuda_bf16.h>
#include <math.h>
#include <stdint.h>

// ---------------- problem constants ----------------
#define BATCH 16
#define HH 112
#define WW 112
#define SS 7
#define DD 3
#define HEADS 6
#define DIM 192
#define HIDDEN 768
#define NWIN 49
#define WIN_PER_IMG 256
#define BW (BATCH * WIN_PER_IMG)   // 4096
#define TOKENS (BW * NWIN)         // 200704
#define HEADDIM 32
#define LPIX (HH * WW)

typedef __nv_bfloat16 bf16;

// ---------------- scratch ----------------
__device__ bf16  g_win[(size_t)TOKENS * DIM];
__device__ bf16  g_q[(size_t)TOKENS * DIM];
__device__ bf16  g_k[(size_t)TOKENS * DIM];
__device__ bf16  g_v[(size_t)TOKENS * DIM];
__device__ bf16  g_att[(size_t)TOKENS * DIM];
__device__ float g_x1[(size_t)TOKENS * DIM];
__device__ bf16  g_h[(size_t)TOKENS * HIDDEN];
__device__ bf16  g_wqkv[3 * DIM * DIM];
__device__ bf16  g_wproj[DIM * DIM];
__device__ bf16  g_wfc1[HIDDEN * DIM];
__device__ bf16  g_wfc2[DIM * HIDDEN];

// ---------------- ptx helpers ----------------
__device__ __forceinline__ uint32_t smem_u32(const void* p) {
    return (uint32_t)__cvta_generic_to_shared(p);
}
__device__ __forceinline__ void cp_async16(uint32_t s, const void* g) {
    asm volatile("cp.async.cg.shared.global [%0], [%1], 16;" :: "r"(s), "l"(g));
}
__device__ __forceinline__ void cp_commit() {
    asm volatile("cp.async.commit_group;");
}
template <int N>
__device__ __forceinline__ void cp_wait() {
    asm volatile("cp.async.wait_group %0;" :: "n"(N));
}
__device__ __forceinline__ void ldsm4(uint32_t& r0, uint32_t& r1, uint32_t& r2,
                                      uint32_t& r3, uint32_t addr) {
    asm volatile("ldmatrix.sync.aligned.m8n8.x4.shared.b16 {%0,%1,%2,%3}, [%4];"
                 : "=r"(r0), "=r"(r1), "=r"(r2), "=r"(r3) : "r"(addr));
}
__device__ __forceinline__ void mma_bf16(float* d, const uint32_t* a, const uint32_t* b) {
    asm volatile(
        "mma.sync.aligned.m16n8k16.row.col.f32.bf16.bf16.f32 "
        "{%0,%1,%2,%3}, {%4,%5,%6,%7}, {%8,%9}, {%0,%1,%2,%3};"
        : "+f"(d[0]), "+f"(d[1]), "+f"(d[2]), "+f"(d[3])
        : "r"(a[0]), "r"(a[1]), "r"(a[2]), "r"(a[3]), "r"(b[0]), "r"(b[1]));
}

// ---------------- weight fp32 -> bf16 convert ----------------
__global__ void cvt_kernel(const float4* __restrict__ src,
                           __nv_bfloat162* __restrict__ dst, int n4) {
    int i = blockIdx.x * 256 + threadIdx.x;
    if (i < n4) {
        float4 v = src[i];
        dst[2 * i]     = __floats2bfloat162_rn(v.x, v.y);
        dst[2 * i + 1] = __floats2bfloat162_rn(v.z, v.w);
    }
}

// ---------------- LayerNorm (one warp per token), bf16 out ----------------
template <bool GATHER>
__global__ void ln_kernel(const float* __restrict__ x,
                          const float* __restrict__ gamma,
                          const float* __restrict__ beta,
                          bf16* __restrict__ out) {
    int warp = (blockIdx.x * blockDim.x + threadIdx.x) >> 5;
    int lane = threadIdx.x & 31;
    if (warp >= TOKENS) return;

    const float* src;
    if (GATHER) {
        int w = warp / NWIN, n = warp - w * NWIN;
        int b = w >> 8, ws = w & 255;
        int wh = ws >> 4, wc = ws & 15;
        int ii = n / SS, jj = n - ii * SS;
        int r = wh * SS + ii + DD; if (r >= HH) r -= HH;
        int c = wc * SS + jj + DD; if (c >= WW) c -= WW;
        src = x + ((size_t)b * LPIX + r * WW + c) * DIM;
    } else {
        src = x + (size_t)warp * DIM;
    }

    float v[6];
    float s = 0.f, s2 = 0.f;
#pragma unroll
    for (int k = 0; k < 6; k++) {
        v[k] = src[lane + 32 * k];
        s += v[k];
        s2 += v[k] * v[k];
    }
#pragma unroll
    for (int o = 16; o > 0; o >>= 1) {
        s  += __shfl_xor_sync(0xffffffffu, s, o);
        s2 += __shfl_xor_sync(0xffffffffu, s2, o);
    }
    float mu = s * (1.0f / DIM);
    float var = s2 * (1.0f / DIM) - mu * mu;
    float rstd = rsqrtf(var + 1e-5f);
    bf16* dst = out + (size_t)warp * DIM;
#pragma unroll
    for (int k = 0; k < 6; k++) {
        int cc = lane + 32 * k;
        dst[cc] = __float2bfloat16_rn((v[k] - mu) * rstd * gamma[cc] + beta[cc]);
    }
}

// ---------------- bf16 tensor-core GEMM ----------------
// C[M,N] = A[M,K] @ W[N,K]^T + bias. Block 256x64x64, 8 warps (4m x 2n),
// 3-stage cp.async pipeline, SW128 swizzled smem, ldmatrix fragments.
// grid = (N/64, M/256) so A streams through L2 once.
// EPI 0: QKV split -> bf16 q(scaled),k,v  [Bw,h,N,d]
// EPI 1: proj -> unshift + residual(x) -> fp32 x1 (image layout)
// EPI 2: GELU -> bf16
// EPI 3: residual -> fp32
#define BM 256
#define BN 64
#define A_STAGE 32768            // BM rows * 128B
#define B_STAGE 8192             // BN rows * 128B
#define STAGE_BYTES (A_STAGE + B_STAGE)
#define GEMM_SMEM (3 * STAGE_BYTES)   // 122880

template <int EPI>
__global__ void __launch_bounds__(256, 1)
gemm_bf16(const bf16* __restrict__ A, const bf16* __restrict__ W,
          const float* __restrict__ bias,
          void* __restrict__ O0, void* __restrict__ O1, void* __restrict__ O2,
          const float* __restrict__ RES, int M, int N, int K) {
    extern __shared__ char sm[];
    const int t = threadIdx.x;
    const int wid = t >> 5, lane = t & 31;
    const int warp_m = wid & 3, warp_n = wid >> 1 >> 1; // wid>>2
    const int m0 = blockIdx.y * BM;
    const int n0 = blockIdx.x * BN;
    const uint32_t sbase = smem_u32(sm);
    const int NT = K >> 6;

    const int lr = lane & 7, g2 = lane >> 3;

    float acc[4][4][4] = {};

    // ---- async tile loader ----
    auto issue = [&](int kt, int s) {
        const char* Ab = (const char*)(A + (size_t)m0 * K + kt * 64);
        uint32_t as = sbase + s * STAGE_BYTES;
#pragma unroll
        for (int i = 0; i < 8; i++) {
            int id = i * 256 + t;
            int row = id >> 3, c = id & 7;
            cp_async16(as + row * 128 + ((c * 16) ^ ((row & 7) << 4)),
                       Ab + (size_t)row * K * 2 + c * 16);
        }
        const char* Bb = (const char*)(W + (size_t)n0 * K + kt * 64);
        uint32_t bs = sbase + s * STAGE_BYTES + A_STAGE;
#pragma unroll
        for (int i = 0; i < 2; i++) {
            int id = i * 256 + t;
            int row = id >> 3, c = id & 7;
            cp_async16(bs + row * 128 + ((c * 16) ^ ((row & 7) << 4)),
                       Bb + (size_t)row * K * 2 + c * 16);
        }
    };

    for (int s = 0; s < 3; s++) {
        if (s < NT) issue(s, s);
        cp_commit();
    }

    for (int kt = 0; kt < NT; kt++) {
        cp_wait<2>();
        __syncthreads();
        int s = kt % 3;
        uint32_t as = sbase + s * STAGE_BYTES;
        uint32_t bs = as + A_STAGE;
#pragma unroll
        for (int ks = 0; ks < 4; ks++) {
            uint32_t a[4][4], b[4][2];
            const int kb = ks * 32;
#pragma unroll
            for (int mf = 0; mf < 4; mf++) {
                int row = warp_m * 64 + mf * 16 + lr + (g2 & 1) * 8;
                int col = kb + (g2 >> 1) * 16;
                ldsm4(a[mf][0], a[mf][1], a[mf][2], a[mf][3],
                      as + row * 128 + (col ^ ((row & 7) << 4)));
            }
#pragma unroll
            for (int p = 0; p < 2; p++) {
                int row = warp_n * 32 + p * 16 + lr + (g2 >> 1) * 8;
                int col = kb + (g2 & 1) * 16;
                uint32_t r0, r1, r2, r3;
                ldsm4(r0, r1, r2, r3, bs + row * 128 + (col ^ ((row & 7) << 4)));
                b[p * 2][0] = r0;     b[p * 2][1] = r1;
                b[p * 2 + 1][0] = r2; b[p * 2 + 1][1] = r3;
            }
#pragma unroll
            for (int mf = 0; mf < 4; mf++)
#pragma unroll
                for (int nf = 0; nf < 4; nf++)
                    mma_bf16(acc[mf][nf], a[mf], b[nf]);
        }
        __syncthreads();
        if (kt + 3 < NT) issue(kt + 3, s);
        cp_commit();
    }

    // ---- epilogue ----
    const int gq = lane >> 2, qq = lane & 3;
#pragma unroll
    for (int mf = 0; mf < 4; mf++) {
#pragma unroll
        for (int nf = 0; nf < 4; nf++) {
#pragma unroll
            for (int half = 0; half < 2; half++) {
                int r = m0 + warp_m * 64 + mf * 16 + gq + half * 8;
                int c = n0 + warp_n * 32 + nf * 8 + 2 * qq;
                float v0 = acc[mf][nf][2 * half + 0] + bias[c];
                float v1 = acc[mf][nf][2 * half + 1] + bias[c + 1];
                if (EPI == 0) {
                    int which = c / DIM;
                    int c2 = c - which * DIM;
                    int hd = c2 >> 5, dd = c2 & 31;
                    int w = r / NWIN, n = r - w * NWIN;
                    size_t off = ((size_t)(w * HEADS + hd) * NWIN + n) * HEADDIM + dd;
                    bf16* dst = (which == 0) ? (bf16*)O0 : (which == 1) ? (bf16*)O1 : (bf16*)O2;
                    if (which == 0) { v0 *= 0.17677669529663687f; v1 *= 0.17677669529663687f; }
                    *(__nv_bfloat162*)(dst + off) = __floats2bfloat162_rn(v0, v1);
                } else if (EPI == 1) {
                    int w = r / NWIN, n = r - w * NWIN;
                    int b = w >> 8, ws = w & 255;
                    int wh = ws >> 4, wc = ws & 15;
                    int ii = n / SS, jj = n - ii * SS;
                    int rr = wh * SS + ii + DD; if (rr >= HH) rr -= HH;
                    int cc = wc * SS + jj + DD; if (cc >= WW) cc -= WW;
                    size_t dst = ((size_t)b * LPIX + rr * WW + cc) * DIM + c;
                    float* o = (float*)O0;
                    o[dst] = v0 + RES[dst];
                    o[dst + 1] = v1 + RES[dst + 1];
                } else if (EPI == 2) {
                    size_t idx = (size_t)r * N + c;
                    float g0 = 0.5f * v0 * (1.0f + erff(v0 * 0.70710678118654752f));
                    float g1 = 0.5f * v1 * (1.0f + erff(v1 * 0.70710678118654752f));
                    *(__nv_bfloat162*)((bf16*)O0 + idx) = __floats2bfloat162_rn(g0, g1);
                } else {
                    size_t idx = (size_t)r * N + c;
                    float* o = (float*)O0;
                    o[idx] = v0 + RES[idx];
                    o[idx + 1] = v1 + RES[idx + 1];
                }
            }
        }
    }
}

// ---------------- fused window attention ----------------
#define QS 36   // padded row stride (floats) -> conflict-free float4 LDS
__global__ void __launch_bounds__(256)
attn_kernel(const bf16* __restrict__ q, const bf16* __restrict__ k,
            const bf16* __restrict__ v, const float* __restrict__ rpe,
            bf16* __restrict__ out) {
    int bh = blockIdx.x;
    int w = bh / HEADS, h = bh - w * HEADS;

    __shared__ float qs[NWIN * QS];
    __shared__ float ks[NWIN * QS];
    __shared__ float vs[NWIN * QS];
    __shared__ float sc[NWIN * NWIN];
    __shared__ int lbl[NWIN];

    const bf16* qp = q + (size_t)bh * NWIN * HEADDIM;
    const bf16* kp = k + (size_t)bh * NWIN * HEADDIM;
    const bf16* vp = v + (size_t)bh * NWIN * HEADDIM;
    int t = threadIdx.x;

    for (int i = t; i < NWIN * HEADDIM; i += 256) {
        int row = i >> 5, d = i & 31;
        qs[row * QS + d] = __bfloat162float(qp[i]);
        ks[row * QS + d] = __bfloat162float(kp[i]);
        vs[row * QS + d] = __bfloat162float(vp[i]);
    }
    if (t < NWIN) {
        int ws = w & 255;
        int wh = ws >> 4, wc = ws & 15;
        int ii = t / SS, jj = t - ii * SS;
        int r = wh * SS + ii, c = wc * SS + jj;
        int rb = r < (HH - SS) ? 0 : (r < (HH - DD) ? 1 : 2);
        int cb = c < (WW - SS) ? 0 : (c < (WW - DD) ? 1 : 2);
        const int LT[9] = {0, 5, 4, 7, 8, 6, 2, 3, 1};
        lbl[t] = LT[rb * 3 + cb];
    }
    __syncthreads();

    for (int idx = t; idx < NWIN * NWIN; idx += 256) {
        int n = idx / NWIN, m = idx - n * NWIN;
        const float4* q4 = (const float4*)&qs[n * QS];
        const float4* k4 = (const float4*)&ks[m * QS];
        float s = 0.f;
#pragma unroll
        for (int i = 0; i < 8; i++) {
            float4 a = q4[i], b = k4[i];
            s += a.x * b.x + a.y * b.y + a.z * b.z + a.w * b.w;
        }
        int di = n / SS - m / SS + (SS - 1);
        int dj = n % SS - m % SS + (SS - 1);
        s += rpe[(di * (2 * SS - 1) + dj) * HEADS + h];
        if (lbl[n] != lbl[m]) s -= 100.0f;
        sc[idx] = s;
    }
    __syncthreads();

    int wid = t >> 5, lane = t & 31;
    for (int row = wid; row < NWIN; row += 8) {
        float mx = -1e30f;
        for (int m = lane; m < NWIN; m += 32) mx = fmaxf(mx, sc[row * NWIN + m]);
#pragma unroll
        for (int o = 16; o > 0; o >>= 1) mx = fmaxf(mx, __shfl_xor_sync(0xffffffffu, mx, o));
        float sum = 0.f;
        for (int m = lane; m < NWIN; m += 32) {
            float e = expf(sc[row * NWIN + m] - mx);
            sc[row * NWIN + m] = e;
            sum += e;
        }
#pragma unroll
        for (int o = 16; o > 0; o >>= 1) sum += __shfl_xor_sync(0xffffffffu, sum, o);
        float inv = 1.0f / sum;
        for (int m = lane; m < NWIN; m += 32) sc[row * NWIN + m] *= inv;
    }
    __syncthreads();

    for (int idx = t; idx < NWIN * HEADDIM; idx += 256) {
        int n = idx >> 5, dd = idx & 31;
        float accv = 0.f;
#pragma unroll
        for (int m = 0; m < NWIN; m++)
            accv += sc[n * NWIN + m] * vs[m * QS + dd];
        out[((size_t)w * NWIN + n) * DIM + h * HEADDIM + dd] = __float2bfloat16_rn(accv);
    }
}

// ---------------- launcher ----------------
extern "C" void kernel_launch(void* const* d_in, const int* in_sizes, int n_in,
                              void* d_out, int out_size) {
    const float* x      = (const float*)d_in[0];
    const float* w_qkv  = (const float*)d_in[1];
    const float* b_qkv  = (const float*)d_in[2];
    const float* w_proj = (const float*)d_in[3];
    const float* b_proj = (const float*)d_in[4];
    const float* rpe    = (const float*)d_in[5];
    const float* gamma1 = (const float*)d_in[6];
    const float* beta1  = (const float*)d_in[7];
    const float* gamma2 = (const float*)d_in[8];
    const float* beta2  = (const float*)d_in[9];
    const float* w_fc1  = (const float*)d_in[10];
    const float* b_fc1  = (const float*)d_in[11];
    const float* w_fc2  = (const float*)d_in[12];
    const float* b_fc2  = (const float*)d_in[13];
    float* out = (float*)d_out;

    bf16 *win, *q, *k, *v, *att, *hbuf, *wqkv, *wproj, *wfc1, *wfc2;
    float* x1;
    cudaGetSymbolAddress((void**)&win,   g_win);
    cudaGetSymbolAddress((void**)&q,     g_q);
    cudaGetSymbolAddress((void**)&k,     g_k);
    cudaGetSymbolAddress((void**)&v,     g_v);
    cudaGetSymbolAddress((void**)&att,   g_att);
    cudaGetSymbolAddress((void**)&x1,    g_x1);
    cudaGetSymbolAddress((void**)&hbuf,  g_h);
    cudaGetSymbolAddress((void**)&wqkv,  g_wqkv);
    cudaGetSymbolAddress((void**)&wproj, g_wproj);
    cudaGetSymbolAddress((void**)&wfc1,  g_wfc1);
    cudaGetSymbolAddress((void**)&wfc2,  g_wfc2);

    cudaFuncSetAttribute(gemm_bf16<0>, cudaFuncAttributeMaxDynamicSharedMemorySize, GEMM_SMEM);
    cudaFuncSetAttribute(gemm_bf16<1>, cudaFuncAttributeMaxDynamicSharedMemorySize, GEMM_SMEM);
    cudaFuncSetAttribute(gemm_bf16<2>, cudaFuncAttributeMaxDynamicSharedMemorySize, GEMM_SMEM);
    cudaFuncSetAttribute(gemm_bf16<3>, cudaFuncAttributeMaxDynamicSharedMemorySize, GEMM_SMEM);

    // 0) weight conversions
    cvt_kernel<<<(3 * DIM * DIM / 4 + 255) / 256, 256>>>(
        (const float4*)w_qkv, (__nv_bfloat162*)wqkv, 3 * DIM * DIM / 4);
    cvt_kernel<<<(DIM * DIM / 4 + 255) / 256, 256>>>(
        (const float4*)w_proj, (__nv_bfloat162*)wproj, DIM * DIM / 4);
    cvt_kernel<<<(HIDDEN * DIM / 4 + 255) / 256, 256>>>(
        (const float4*)w_fc1, (__nv_bfloat162*)wfc1, HIDDEN * DIM / 4);
    cvt_kernel<<<(DIM * HIDDEN / 4 + 255) / 256, 256>>>(
        (const float4*)w_fc2, (__nv_bfloat162*)wfc2, DIM * HIDDEN / 4);

    const int LN_BLOCKS = TOKENS / 8;
    const int MT = TOKENS / BM;   // 784

    // 1) LN1 + shift + window gather
    ln_kernel<true><<<LN_BLOCKS, 256>>>(x, gamma1, beta1, win);

    // 2) QKV GEMM (N=576)
    gemm_bf16<0><<<dim3(576 / BN, MT), 256, GEMM_SMEM>>>(
        win, wqkv, b_qkv, q, k, v, nullptr, TOKENS, 3 * DIM, DIM);

    // 3) windowed attention
    attn_kernel<<<BW * HEADS, 256>>>(q, k, v, rpe, att);

    // 4) proj GEMM + unshift + residual -> x1 (fp32)
    gemm_bf16<1><<<dim3(DIM / BN, MT), 256, GEMM_SMEM>>>(
        att, wproj, b_proj, x1, nullptr, nullptr, x, TOKENS, DIM, DIM);

    // 5) LN2 -> bf16
    ln_kernel<false><<<LN_BLOCKS, 256>>>(x1, gamma2, beta2, win);

    // 6) fc1 GEMM + GELU (N=768) -> bf16
    gemm_bf16<2><<<dim3(HIDDEN / BN, MT), 256, GEMM_SMEM>>>(
        win, wfc1, b_fc1, hbuf, nullptr, nullptr, nullptr, TOKENS, HIDDEN, DIM);

    // 7) fc2 GEMM + residual(x1) -> fp32 d_out (K=768)
    gemm_bf16<3><<<dim3(DIM / BN, MT), 256, GEMM_SMEM>>>(
        hbuf, wfc2, b_fc2, out, nullptr, nullptr, x1, TOKENS, DIM, HIDDEN);
}

// round 4
// speedup vs baseline: 5.7579x; 1.7080x over previous
#include <cuda_runtime.h>
#include <cuda_bf16.h>
#include <math.h>
#include <stdint.h>

// ---------------- problem constants ----------------
#define BATCH 16
#define HH 112
#define WW 112
#define SS 7
#define DD 3
#define HEADS 6
#define DIM 192
#define HIDDEN 768
#define NWIN 49
#define WIN_PER_IMG 256
#define BW (BATCH * WIN_PER_IMG)   // 4096
#define TOKENS (BW * NWIN)         // 200704
#define HEADDIM 32
#define LPIX (HH * WW)

typedef __nv_bfloat16 bf16;

// ---------------- scratch ----------------
__device__ bf16  g_win[(size_t)TOKENS * DIM];
__device__ bf16  g_q[(size_t)TOKENS * DIM];
__device__ bf16  g_k[(size_t)TOKENS * DIM];
__device__ bf16  g_v[(size_t)TOKENS * DIM];
__device__ bf16  g_att[(size_t)TOKENS * DIM];
__device__ float g_x1[(size_t)TOKENS * DIM];
__device__ bf16  g_h[(size_t)TOKENS * HIDDEN];
__device__ bf16  g_wqkv[3 * DIM * DIM];
__device__ bf16  g_wproj[DIM * DIM];
__device__ bf16  g_wfc1[HIDDEN * DIM];
__device__ bf16  g_wfc2[DIM * HIDDEN];

// ---------------- ptx helpers ----------------
__device__ __forceinline__ uint32_t smem_u32(const void* p) {
    return (uint32_t)__cvta_generic_to_shared(p);
}
__device__ __forceinline__ void cp_async16(uint32_t s, const void* g) {
    asm volatile("cp.async.cg.shared.global [%0], [%1], 16;" :: "r"(s), "l"(g));
}
__device__ __forceinline__ void cp_commit() {
    asm volatile("cp.async.commit_group;");
}
template <int N>
__device__ __forceinline__ void cp_wait() {
    asm volatile("cp.async.wait_group %0;" :: "n"(N));
}
__device__ __forceinline__ void ldsm4(uint32_t& r0, uint32_t& r1, uint32_t& r2,
                                      uint32_t& r3, uint32_t addr) {
    asm volatile("ldmatrix.sync.aligned.m8n8.x4.shared.b16 {%0,%1,%2,%3}, [%4];"
                 : "=r"(r0), "=r"(r1), "=r"(r2), "=r"(r3) : "r"(addr));
}
__device__ __forceinline__ void ldsm4t(uint32_t& r0, uint32_t& r1, uint32_t& r2,
                                       uint32_t& r3, uint32_t addr) {
    asm volatile("ldmatrix.sync.aligned.m8n8.x4.trans.shared.b16 {%0,%1,%2,%3}, [%4];"
                 : "=r"(r0), "=r"(r1), "=r"(r2), "=r"(r3) : "r"(addr));
}
__device__ __forceinline__ void mma_bf16(float* d, const uint32_t* a, const uint32_t* b) {
    asm volatile(
        "mma.sync.aligned.m16n8k16.row.col.f32.bf16.bf16.f32 "
        "{%0,%1,%2,%3}, {%4,%5,%6,%7}, {%8,%9}, {%0,%1,%2,%3};"
        : "+f"(d[0]), "+f"(d[1]), "+f"(d[2]), "+f"(d[3])
        : "r"(a[0]), "r"(a[1]), "r"(a[2]), "r"(a[3]), "r"(b[0]), "r"(b[1]));
}
__device__ __forceinline__ uint32_t packbf(float a, float b) {
    __nv_bfloat162 t = __floats2bfloat162_rn(a, b);
    return *(uint32_t*)&t;
}

// ---------------- weight fp32 -> bf16 convert (all weights, 1 launch) ------
#define N4_QKV (3 * DIM * DIM / 4)
#define N4_PROJ (DIM * DIM / 4)
#define N4_FC1 (HIDDEN * DIM / 4)
#define N4_FC2 (DIM * HIDDEN / 4)
#define N4_ALL (N4_QKV + N4_PROJ + N4_FC1 + N4_FC2)
__global__ void cvt_all(const float4* s0, const float4* s1, const float4* s2,
                        const float4* s3, __nv_bfloat162* d0, __nv_bfloat162* d1,
                        __nv_bfloat162* d2, __nv_bfloat162* d3) {
    int i = blockIdx.x * 256 + threadIdx.x;
    const float4* s; __nv_bfloat162* d; int j = i;
    if (j < N4_QKV) { s = s0; d = d0; }
    else if ((j -= N4_QKV) < N4_PROJ) { s = s1; d = d1; }
    else if ((j -= N4_PROJ) < N4_FC1) { s = s2; d = d2; }
    else if ((j -= N4_FC1) < N4_FC2) { s = s3; d = d3; }
    else return;
    float4 v = s[j];
    d[2 * j]     = __floats2bfloat162_rn(v.x, v.y);
    d[2 * j + 1] = __floats2bfloat162_rn(v.z, v.w);
}

// ---------------- LayerNorm (one warp per token), bf16 out ----------------
template <bool GATHER>
__global__ void ln_kernel(const float* __restrict__ x,
                          const float* __restrict__ gamma,
                          const float* __restrict__ beta,
                          bf16* __restrict__ out) {
    int warp = (blockIdx.x * blockDim.x + threadIdx.x) >> 5;
    int lane = threadIdx.x & 31;
    if (warp >= TOKENS) return;

    const float* src;
    if (GATHER) {
        int w = warp / NWIN, n = warp - w * NWIN;
        int b = w >> 8, ws = w & 255;
        int wh = ws >> 4, wc = ws & 15;
        int ii = n / SS, jj = n - ii * SS;
        int r = wh * SS + ii + DD; if (r >= HH) r -= HH;
        int c = wc * SS + jj + DD; if (c >= WW) c -= WW;
        src = x + ((size_t)b * LPIX + r * WW + c) * DIM;
    } else {
        src = x + (size_t)warp * DIM;
    }

    float v[6];
    float s = 0.f, s2 = 0.f;
#pragma unroll
    for (int k = 0; k < 6; k++) {
        v[k] = src[lane + 32 * k];
        s += v[k];
        s2 += v[k] * v[k];
    }
#pragma unroll
    for (int o = 16; o > 0; o >>= 1) {
        s  += __shfl_xor_sync(0xffffffffu, s, o);
        s2 += __shfl_xor_sync(0xffffffffu, s2, o);
    }
    float mu = s * (1.0f / DIM);
    float var = s2 * (1.0f / DIM) - mu * mu;
    float rstd = rsqrtf(var + 1e-5f);
    bf16* dst = out + (size_t)warp * DIM;
#pragma unroll
    for (int k = 0; k < 6; k++) {
        int cc = lane + 32 * k;
        dst[cc] = __float2bfloat16_rn((v[k] - mu) * rstd * gamma[cc] + beta[cc]);
    }
}

// ---------------- bf16 tensor-core GEMM ----------------
// C[M,N] = A[M,K] @ W[N,K]^T + bias. Block 128x64x64, 8 warps (4m x 2n),
// 3-stage cp.async pipeline, SW128 swizzle, ldmatrix fragments.
#define BM 128
#define BN 64
#define A_STAGE 16384            // BM rows * 128B
#define B_STAGE 8192             // BN rows * 128B
#define STAGE_BYTES (A_STAGE + B_STAGE)
#define GEMM_SMEM (3 * STAGE_BYTES)   // 73728

template <int EPI>
__global__ void __launch_bounds__(256, 2)
gemm_bf16(const bf16* __restrict__ A, const bf16* __restrict__ W,
          const float* __restrict__ bias,
          void* __restrict__ O0, void* __restrict__ O1, void* __restrict__ O2,
          const float* __restrict__ RES, int M, int N, int K) {
    extern __shared__ char sm[];
    const int t = threadIdx.x;
    const int wid = t >> 5, lane = t & 31;
    const int warp_m = wid & 3, warp_n = wid >> 2;
    const int m0 = blockIdx.y * BM;
    const int n0 = blockIdx.x * BN;
    const uint32_t sbase = smem_u32(sm);
    const int NT = K >> 6;

    const int lr = lane & 7, g2 = lane >> 3;

    float acc[2][4][4] = {};

    auto issue = [&](int kt, int s) {
        const char* Ab = (const char*)(A + (size_t)m0 * K + kt * 64);
        uint32_t as = sbase + s * STAGE_BYTES;
#pragma unroll
        for (int i = 0; i < 4; i++) {
            int id = i * 256 + t;
            int row = id >> 3, c = id & 7;
            cp_async16(as + row * 128 + ((c * 16) ^ ((row & 7) << 4)),
                       Ab + (size_t)row * K * 2 + c * 16);
        }
        const char* Bb = (const char*)(W + (size_t)n0 * K + kt * 64);
        uint32_t bs = sbase + s * STAGE_BYTES + A_STAGE;
#pragma unroll
        for (int i = 0; i < 2; i++) {
            int id = i * 256 + t;
            int row = id >> 3, c = id & 7;
            cp_async16(bs + row * 128 + ((c * 16) ^ ((row & 7) << 4)),
                       Bb + (size_t)row * K * 2 + c * 16);
        }
    };

    for (int s = 0; s < 3; s++) {
        if (s < NT) issue(s, s);
        cp_commit();
    }

    for (int kt = 0; kt < NT; kt++) {
        cp_wait<2>();
        __syncthreads();
        int s = kt % 3;
        uint32_t as = sbase + s * STAGE_BYTES;
        uint32_t bs = as + A_STAGE;
#pragma unroll
        for (int ks = 0; ks < 4; ks++) {
            uint32_t a[2][4], b[4][2];
            const int kb = ks * 32;
#pragma unroll
            for (int mf = 0; mf < 2; mf++) {
                int row = warp_m * 32 + mf * 16 + lr + (g2 & 1) * 8;
                int col = kb + (g2 >> 1) * 16;
                ldsm4(a[mf][0], a[mf][1], a[mf][2], a[mf][3],
                      as + row * 128 + (col ^ ((row & 7) << 4)));
            }
#pragma unroll
            for (int p = 0; p < 2; p++) {
                int row = warp_n * 32 + p * 16 + lr + (g2 >> 1) * 8;
                int col = kb + (g2 & 1) * 16;
                uint32_t r0, r1, r2, r3;
                ldsm4(r0, r1, r2, r3, bs + row * 128 + (col ^ ((row & 7) << 4)));
                b[p * 2][0] = r0;     b[p * 2][1] = r1;
                b[p * 2 + 1][0] = r2; b[p * 2 + 1][1] = r3;
            }
#pragma unroll
            for (int mf = 0; mf < 2; mf++)
#pragma unroll
                for (int nf = 0; nf < 4; nf++)
                    mma_bf16(acc[mf][nf], a[mf], b[nf]);
        }
        __syncthreads();
        if (kt + 3 < NT) issue(kt + 3, s);
        cp_commit();
    }

    const int gq = lane >> 2, qq = lane & 3;
#pragma unroll
    for (int mf = 0; mf < 2; mf++) {
#pragma unroll
        for (int nf = 0; nf < 4; nf++) {
#pragma unroll
            for (int half = 0; half < 2; half++) {
                int r = m0 + warp_m * 32 + mf * 16 + gq + half * 8;
                int c = n0 + warp_n * 32 + nf * 8 + 2 * qq;
                float v0 = acc[mf][nf][2 * half + 0] + bias[c];
                float v1 = acc[mf][nf][2 * half + 1] + bias[c + 1];
                if (EPI == 0) {
                    int which = c / DIM;
                    int c2 = c - which * DIM;
                    int hd = c2 >> 5, dd = c2 & 31;
                    int w = r / NWIN, n = r - w * NWIN;
                    size_t off = ((size_t)(w * HEADS + hd) * NWIN + n) * HEADDIM + dd;
                    bf16* dst = (which == 0) ? (bf16*)O0 : (which == 1) ? (bf16*)O1 : (bf16*)O2;
                    if (which == 0) { v0 *= 0.17677669529663687f; v1 *= 0.17677669529663687f; }
                    *(__nv_bfloat162*)(dst + off) = __floats2bfloat162_rn(v0, v1);
                } else if (EPI == 1) {
                    int w = r / NWIN, n = r - w * NWIN;
                    int b = w >> 8, ws = w & 255;
                    int wh = ws >> 4, wc = ws & 15;
                    int ii = n / SS, jj = n - ii * SS;
                    int rr = wh * SS + ii + DD; if (rr >= HH) rr -= HH;
                    int cc = wc * SS + jj + DD; if (cc >= WW) cc -= WW;
                    size_t dst = ((size_t)b * LPIX + rr * WW + cc) * DIM + c;
                    float* o = (float*)O0;
                    o[dst] = v0 + RES[dst];
                    o[dst + 1] = v1 + RES[dst + 1];
                } else if (EPI == 2) {
                    size_t idx = (size_t)r * N + c;
                    float g0 = 0.5f * v0 * (1.0f + erff(v0 * 0.70710678118654752f));
                    float g1 = 0.5f * v1 * (1.0f + erff(v1 * 0.70710678118654752f));
                    *(__nv_bfloat162*)((bf16*)O0 + idx) = __floats2bfloat162_rn(g0, g1);
                } else {
                    size_t idx = (size_t)r * N + c;
                    float* o = (float*)O0;
                    o[idx] = v0 + RES[idx];
                    o[idx + 1] = v1 + RES[idx + 1];
                }
            }
        }
    }
}

// ---------------- attention via mma: one block per (window, head) ----------
// 4 warps. S = QK^T (64x56 padded, 7 n8-tiles), register softmax,
// P kept in registers as A-fragments, PV via ldmatrix.trans on V.
#define AST 40   // smem row stride in bf16 (80B): conflict-free ldmatrix
__global__ void __launch_bounds__(128)
attn_kernel(const bf16* __restrict__ q, const bf16* __restrict__ k,
            const bf16* __restrict__ v, const float* __restrict__ rpe,
            bf16* __restrict__ out) {
    int bh = blockIdx.x;
    int w = bh / HEADS, h = bh - w * HEADS;

    __shared__ bf16 qs[64 * AST];
    __shared__ bf16 ks[64 * AST];
    __shared__ bf16 vs[64 * AST];
    __shared__ int lbl[NWIN];

    const int t = threadIdx.x;
    const int wm = t >> 5, lane = t & 31;

    // load q,k,v (49 rows) + zero pad to 64 rows
    {
        const uint4* qg = (const uint4*)(q + (size_t)bh * NWIN * HEADDIM);
        const uint4* kg = (const uint4*)(k + (size_t)bh * NWIN * HEADDIM);
        const uint4* vg = (const uint4*)(v + (size_t)bh * NWIN * HEADDIM);
        const uint4 zz = make_uint4(0, 0, 0, 0);
#pragma unroll
        for (int it = 0; it < 2; it++) {
            int task = it * 128 + t;
            int row = task >> 2, seg = task & 3;
            bool ok = row < NWIN;
            *(uint4*)&qs[row * AST + seg * 8] = ok ? qg[row * 4 + seg] : zz;
            *(uint4*)&ks[row * AST + seg * 8] = ok ? kg[row * 4 + seg] : zz;
            *(uint4*)&vs[row * AST + seg * 8] = ok ? vg[row * 4 + seg] : zz;
        }
    }
    if (t < NWIN) {
        int ws = w & 255;
        int wh = ws >> 4, wc = ws & 15;
        int ii = t / SS, jj = t - ii * SS;
        int r = wh * SS + ii, c = wc * SS + jj;
        int rb = r < (HH - SS) ? 0 : (r < (HH - DD) ? 1 : 2);
        int cb = c < (WW - SS) ? 0 : (c < (WW - DD) ? 1 : 2);
        const int LT[9] = {0, 5, 4, 7, 8, 6, 2, 3, 1};
        lbl[t] = LT[rb * 3 + cb];
    }
    __syncthreads();

    const uint32_t sq = smem_u32(qs), sk = smem_u32(ks), sv = smem_u32(vs);
    const int sub = lane >> 3, l7 = lane & 7;

    // ---- scores ----
    float c[7][4] = {};
#pragma unroll
    for (int kc = 0; kc < 2; kc++) {
        uint32_t a[4];
        {
            int row = wm * 16 + (sub & 1) * 8 + l7;
            int col = kc * 32 + (sub >> 1) * 16;
            ldsm4(a[0], a[1], a[2], a[3], sq + row * (AST * 2) + col);
        }
#pragma unroll
        for (int p = 0; p < 4; p++) {
            int n = p * 16 + (sub >> 1) * 8 + l7;
            int col = kc * 32 + (sub & 1) * 16;
            uint32_t r0, r1, r2, r3;
            ldsm4(r0, r1, r2, r3, sk + n * (AST * 2) + col);
            uint32_t b0[2] = {r0, r1};
            mma_bf16(c[2 * p], a, b0);
            if (p < 3) {
                uint32_t b1[2] = {r2, r3};
                mma_bf16(c[2 * p + 1], a, b1);
            }
        }
    }

    // ---- RPE + mask + register softmax ----
    const int g = lane >> 2, qd = lane & 3;
    const int row0 = wm * 16 + g, row1 = row0 + 8;
    const int rr0 = row0 < NWIN ? row0 : 0;
    const int rr1 = row1 < NWIN ? row1 : 0;
    const int l0 = lbl[rr0], l1 = lbl[rr1];
    const int r0i = rr0 / SS, r0j = rr0 - r0i * SS;
    const int r1i = rr1 / SS, r1j = rr1 - r1i * SS;
#pragma unroll
    for (int tt = 0; tt < 7; tt++) {
#pragma unroll
        for (int e = 0; e < 4; e++) {
            int col = tt * 8 + 2 * qd + (e & 1);
            if (col < NWIN) {
                int ci = col / SS, cj = col - ci * SS;
                int ri = (e < 2) ? r0i : r1i, rj = (e < 2) ? r0j : r1j;
                int ll = (e < 2) ? l0 : l1;
                float add = rpe[((ri - ci + 6) * 13 + (rj - cj + 6)) * HEADS + h];
                if (ll != lbl[col]) add -= 100.0f;
                c[tt][e] += add;
            } else {
                c[tt][e] = -1e30f;
            }
        }
    }
    // row0 softmax (c[t][0], c[t][1])
    {
        float mx = -1e30f;
#pragma unroll
        for (int tt = 0; tt < 7; tt++) mx = fmaxf(mx, fmaxf(c[tt][0], c[tt][1]));
        mx = fmaxf(mx, __shfl_xor_sync(0xffffffffu, mx, 1));
        mx = fmaxf(mx, __shfl_xor_sync(0xffffffffu, mx, 2));
        float sum = 0.f;
#pragma unroll
        for (int tt = 0; tt < 7; tt++) {
            c[tt][0] = __expf(c[tt][0] - mx); sum += c[tt][0];
            c[tt][1] = __expf(c[tt][1] - mx); sum += c[tt][1];
        }
        sum += __shfl_xor_sync(0xffffffffu, sum, 1);
        sum += __shfl_xor_sync(0xffffffffu, sum, 2);
        float inv = 1.0f / sum;
#pragma unroll
        for (int tt = 0; tt < 7; tt++) { c[tt][0] *= inv; c[tt][1] *= inv; }
    }
    // row1 softmax (c[t][2], c[t][3])
    {
        float mx = -1e30f;
#pragma unroll
        for (int tt = 0; tt < 7; tt++) mx = fmaxf(mx, fmaxf(c[tt][2], c[tt][3]));
        mx = fmaxf(mx, __shfl_xor_sync(0xffffffffu, mx, 1));
        mx = fmaxf(mx, __shfl_xor_sync(0xffffffffu, mx, 2));
        float sum = 0.f;
#pragma unroll
        for (int tt = 0; tt < 7; tt++) {
            c[tt][2] = __expf(c[tt][2] - mx); sum += c[tt][2];
            c[tt][3] = __expf(c[tt][3] - mx); sum += c[tt][3];
        }
        sum += __shfl_xor_sync(0xffffffffu, sum, 1);
        sum += __shfl_xor_sync(0xffffffffu, sum, 2);
        float inv = 1.0f / sum;
#pragma unroll
        for (int tt = 0; tt < 7; tt++) { c[tt][2] *= inv; c[tt][3] *= inv; }
    }

    // ---- PV ----
    float o[4][4] = {};
#pragma unroll
    for (int kc = 0; kc < 4; kc++) {
        uint32_t a[4];
        a[0] = packbf(c[2 * kc][0], c[2 * kc][1]);
        a[1] = packbf(c[2 * kc][2], c[2 * kc][3]);
        if (2 * kc + 1 < 7) {
            a[2] = packbf(c[2 * kc + 1][0], c[2 * kc + 1][1]);
            a[3] = packbf(c[2 * kc + 1][2], c[2 * kc + 1][3]);
        } else {
            a[2] = 0; a[3] = 0;
        }
#pragma unroll
        for (int p = 0; p < 2; p++) {
            int row = kc * 16 + (sub & 1) * 8 + l7;
            int col = p * 32 + (sub >> 1) * 16;
            uint32_t r0, r1, r2, r3;
            ldsm4t(r0, r1, r2, r3, sv + row * (AST * 2) + col);
            uint32_t b0[2] = {r0, r1}, b1[2] = {r2, r3};
            mma_bf16(o[2 * p], a, b0);
            mma_bf16(o[2 * p + 1], a, b1);
        }
    }

    // ---- write out (rows < 49) ----
    bf16* ob = out + (size_t)w * NWIN * DIM + h * HEADDIM;
    if (row0 < NWIN) {
#pragma unroll
        for (int nt = 0; nt < 4; nt++) {
            __nv_bfloat162 pv = __floats2bfloat162_rn(o[nt][0], o[nt][1]);
            *(__nv_bfloat162*)&ob[(size_t)row0 * DIM + nt * 8 + 2 * qd] = pv;
        }
    }
    if (row1 < NWIN) {
#pragma unroll
        for (int nt = 0; nt < 4; nt++) {
            __nv_bfloat162 pv = __floats2bfloat162_rn(o[nt][2], o[nt][3]);
            *(__nv_bfloat162*)&ob[(size_t)row1 * DIM + nt * 8 + 2 * qd] = pv;
        }
    }
}

// ---------------- launcher ----------------
extern "C" void kernel_launch(void* const* d_in, const int* in_sizes, int n_in,
                              void* d_out, int out_size) {
    const float* x      = (const float*)d_in[0];
    const float* w_qkv  = (const float*)d_in[1];
    const float* b_qkv  = (const float*)d_in[2];
    const float* w_proj = (const float*)d_in[3];
    const float* b_proj = (const float*)d_in[4];
    const float* rpe    = (const float*)d_in[5];
    const float* gamma1 = (const float*)d_in[6];
    const float* beta1  = (const float*)d_in[7];
    const float* gamma2 = (const float*)d_in[8];
    const float* beta2  = (const float*)d_in[9];
    const float* w_fc1  = (const float*)d_in[10];
    const float* b_fc1  = (const float*)d_in[11];
    const float* w_fc2  = (const float*)d_in[12];
    const float* b_fc2  = (const float*)d_in[13];
    float* out = (float*)d_out;

    bf16 *win, *q, *k, *v, *att, *hbuf, *wqkv, *wproj, *wfc1, *wfc2;
    float* x1;
    cudaGetSymbolAddress((void**)&win,   g_win);
    cudaGetSymbolAddress((void**)&q,     g_q);
    cudaGetSymbolAddress((void**)&k,     g_k);
    cudaGetSymbolAddress((void**)&v,     g_v);
    cudaGetSymbolAddress((void**)&att,   g_att);
    cudaGetSymbolAddress((void**)&x1,    g_x1);
    cudaGetSymbolAddress((void**)&hbuf,  g_h);
    cudaGetSymbolAddress((void**)&wqkv,  g_wqkv);
    cudaGetSymbolAddress((void**)&wproj, g_wproj);
    cudaGetSymbolAddress((void**)&wfc1,  g_wfc1);
    cudaGetSymbolAddress((void**)&wfc2,  g_wfc2);

    cudaFuncSetAttribute(gemm_bf16<0>, cudaFuncAttributeMaxDynamicSharedMemorySize, GEMM_SMEM);
    cudaFuncSetAttribute(gemm_bf16<1>, cudaFuncAttributeMaxDynamicSharedMemorySize, GEMM_SMEM);
    cudaFuncSetAttribute(gemm_bf16<2>, cudaFuncAttributeMaxDynamicSharedMemorySize, GEMM_SMEM);
    cudaFuncSetAttribute(gemm_bf16<3>, cudaFuncAttributeMaxDynamicSharedMemorySize, GEMM_SMEM);

    // 0) all weight conversions in one launch
    cvt_all<<<(N4_ALL + 255) / 256, 256>>>(
        (const float4*)w_qkv, (const float4*)w_proj, (const float4*)w_fc1,
        (const float4*)w_fc2, (__nv_bfloat162*)wqkv, (__nv_bfloat162*)wproj,
        (__nv_bfloat162*)wfc1, (__nv_bfloat162*)wfc2);

    const int LN_BLOCKS = TOKENS / 8;
    const int MT = TOKENS / BM;   // 1568

    // 1) LN1 + shift + window gather
    ln_kernel<true><<<LN_BLOCKS, 256>>>(x, gamma1, beta1, win);

    // 2) QKV GEMM (N=576)
    gemm_bf16<0><<<dim3(576 / BN, MT), 256, GEMM_SMEM>>>(
        win, wqkv, b_qkv, q, k, v, nullptr, TOKENS, 3 * DIM, DIM);

    // 3) windowed attention (mma)
    attn_kernel<<<BW * HEADS, 128>>>(q, k, v, rpe, att);

    // 4) proj GEMM + unshift + residual -> x1 (fp32)
    gemm_bf16<1><<<dim3(DIM / BN, MT), 256, GEMM_SMEM>>>(
        att, wproj, b_proj, x1, nullptr, nullptr, x, TOKENS, DIM, DIM);

    // 5) LN2 -> bf16
    ln_kernel<false><<<LN_BLOCKS, 256>>>(x1, gamma2, beta2, win);

    // 6) fc1 GEMM + GELU (N=768) -> bf16
    gemm_bf16<2><<<dim3(HIDDEN / BN, MT), 256, GEMM_SMEM>>>(
        win, wfc1, b_fc1, hbuf, nullptr, nullptr, nullptr, TOKENS, HIDDEN, DIM);

    // 7) fc2 GEMM + residual(x1) -> fp32 d_out (K=768)
    gemm_bf16<3><<<dim3(DIM / BN, MT), 256, GEMM_SMEM>>>(
        hbuf, wfc2, b_fc2, out, nullptr, nullptr, x1, TOKENS, DIM, HIDDEN);
}

// round 7
// speedup vs baseline: 6.1872x; 1.0746x over previous
#include <cuda_runtime.h>
#include <cuda_bf16.h>
#include <math.h>
#include <stdint.h>

// ---------------- problem constants ----------------
#define BATCH 16
#define HH 112
#define WW 112
#define SS 7
#define DD 3
#define HEADS 6
#define DIM 192
#define HIDDEN 768
#define NWIN 49
#define WIN_PER_IMG 256
#define BW (BATCH * WIN_PER_IMG)   // 4096
#define TOKENS (BW * NWIN)         // 200704
#define HEADDIM 32
#define LPIX (HH * WW)

typedef __nv_bfloat16 bf16;

// ---------------- scratch ----------------
__device__ bf16  g_win[(size_t)TOKENS * DIM];
__device__ bf16  g_q[(size_t)TOKENS * DIM];
__device__ bf16  g_k[(size_t)TOKENS * DIM];
__device__ bf16  g_v[(size_t)TOKENS * DIM];
__device__ bf16  g_att[(size_t)TOKENS * DIM];
__device__ float g_x1[(size_t)TOKENS * DIM];
__device__ bf16  g_h[(size_t)TOKENS * HIDDEN];
__device__ bf16  g_wqkv[3 * DIM * DIM];
__device__ bf16  g_wproj[DIM * DIM];
__device__ bf16  g_wfc1[HIDDEN * DIM];
__device__ bf16  g_wfc2[DIM * HIDDEN];

// ---------------- ptx helpers ----------------
__device__ __forceinline__ uint32_t smem_u32(const void* p) {
    return (uint32_t)__cvta_generic_to_shared(p);
}
__device__ __forceinline__ void cp_async16(uint32_t s, const void* g) {
    asm volatile("cp.async.cg.shared.global [%0], [%1], 16;" :: "r"(s), "l"(g));
}
__device__ __forceinline__ void cp_commit() {
    asm volatile("cp.async.commit_group;");
}
template <int N>
__device__ __forceinline__ void cp_wait() {
    asm volatile("cp.async.wait_group %0;" :: "n"(N));
}
__device__ __forceinline__ void ldsm4(uint32_t& r0, uint32_t& r1, uint32_t& r2,
                                      uint32_t& r3, uint32_t addr) {
    asm volatile("ldmatrix.sync.aligned.m8n8.x4.shared.b16 {%0,%1,%2,%3}, [%4];"
                 : "=r"(r0), "=r"(r1), "=r"(r2), "=r"(r3) : "r"(addr));
}
__device__ __forceinline__ void ldsm4t(uint32_t& r0, uint32_t& r1, uint32_t& r2,
                                       uint32_t& r3, uint32_t addr) {
    asm volatile("ldmatrix.sync.aligned.m8n8.x4.trans.shared.b16 {%0,%1,%2,%3}, [%4];"
                 : "=r"(r0), "=r"(r1), "=r"(r2), "=r"(r3) : "r"(addr));
}
__device__ __forceinline__ void mma_bf16(float* d, const uint32_t* a, const uint32_t* b) {
    asm volatile(
        "mma.sync.aligned.m16n8k16.row.col.f32.bf16.bf16.f32 "
        "{%0,%1,%2,%3}, {%4,%5,%6,%7}, {%8,%9}, {%0,%1,%2,%3};"
        : "+f"(d[0]), "+f"(d[1]), "+f"(d[2]), "+f"(d[3])
        : "r"(a[0]), "r"(a[1]), "r"(a[2]), "r"(a[3]), "r"(b[0]), "r"(b[1]));
}
__device__ __forceinline__ uint32_t packbf(float a, float b) {
    __nv_bfloat162 t = __floats2bfloat162_rn(a, b);
    return *(uint32_t*)&t;
}

// ---------------- weight fp32 -> bf16 convert (all weights, 1 launch) ------
#define N4_QKV (3 * DIM * DIM / 4)
#define N4_PROJ (DIM * DIM / 4)
#define N4_FC1 (HIDDEN * DIM / 4)
#define N4_FC2 (DIM * HIDDEN / 4)
#define N4_ALL (N4_QKV + N4_PROJ + N4_FC1 + N4_FC2)
__global__ void cvt_all(const float4* s0, const float4* s1, const float4* s2,
                        const float4* s3, __nv_bfloat162* d0, __nv_bfloat162* d1,
                        __nv_bfloat162* d2, __nv_bfloat162* d3) {
    int i = blockIdx.x * 256 + threadIdx.x;
    const float4* s; __nv_bfloat162* d; int j = i;
    if (j < N4_QKV) { s = s0; d = d0; }
    else if ((j -= N4_QKV) < N4_PROJ) { s = s1; d = d1; }
    else if ((j -= N4_PROJ) < N4_FC1) { s = s2; d = d2; }
    else if ((j -= N4_FC1) < N4_FC2) { s = s3; d = d3; }
    else return;
    float4 v = s[j];
    d[2 * j]     = __floats2bfloat162_rn(v.x, v.y);
    d[2 * j + 1] = __floats2bfloat162_rn(v.z, v.w);
}

// ---------------- LayerNorm (one warp per token), bf16 out ----------------
template <bool GATHER>
__global__ void ln_kernel(const float* __restrict__ x,
                          const float* __restrict__ gamma,
                          const float* __restrict__ beta,
                          bf16* __restrict__ out) {
    int warp = (blockIdx.x * blockDim.x + threadIdx.x) >> 5;
    int lane = threadIdx.x & 31;
    if (warp >= TOKENS) return;

    const float* src;
    if (GATHER) {
        int w = warp / NWIN, n = warp - w * NWIN;
        int b = w >> 8, ws = w & 255;
        int wh = ws >> 4, wc = ws & 15;
        int ii = n / SS, jj = n - ii * SS;
        int r = wh * SS + ii + DD; if (r >= HH) r -= HH;
        int c = wc * SS + jj + DD; if (c >= WW) c -= WW;
        src = x + ((size_t)b * LPIX + r * WW + c) * DIM;
    } else {
        src = x + (size_t)warp * DIM;
    }

    float v[6];
    float s = 0.f, s2 = 0.f;
#pragma unroll
    for (int k = 0; k < 6; k++) {
        v[k] = src[lane + 32 * k];
        s += v[k];
        s2 += v[k] * v[k];
    }
#pragma unroll
    for (int o = 16; o > 0; o >>= 1) {
        s  += __shfl_xor_sync(0xffffffffu, s, o);
        s2 += __shfl_xor_sync(0xffffffffu, s2, o);
    }
    float mu = s * (1.0f / DIM);
    float var = s2 * (1.0f / DIM) - mu * mu;
    float rstd = rsqrtf(var + 1e-5f);
    bf16* dst = out + (size_t)warp * DIM;
#pragma unroll
    for (int k = 0; k < 6; k++) {
        int cc = lane + 32 * k;
        dst[cc] = __float2bfloat16_rn((v[k] - mu) * rstd * gamma[cc] + beta[cc]);
    }
}

// ---------------- bf16 tensor-core GEMM ----------------
// C[M,N] = A[M,K] @ W[N,K]^T + bias. Block 128x96x64, 8 warps (4m x 2n),
// warp tile 32x48. 3-stage cp.async pipeline, SW128 swizzle, ldmatrix frags.
#define BM 128
#define BN 96
#define A_STAGE 16384            // BM rows * 128B
#define B_STAGE 12288            // BN rows * 128B
#define STAGE_BYTES (A_STAGE + B_STAGE)       // 28672
#define GEMM_SMEM (3 * STAGE_BYTES)           // 86016

template <int EPI>
__global__ void __launch_bounds__(256, 2)
gemm_bf16(const bf16* __restrict__ A, const bf16* __restrict__ W,
          const float* __restrict__ bias,
          void* __restrict__ O0, void* __restrict__ O1, void* __restrict__ O2,
          const float* __restrict__ RES, int M, int N, int K) {
    extern __shared__ char sm[];
    const int t = threadIdx.x;
    const int wid = t >> 5, lane = t & 31;
    const int warp_m = wid & 3, warp_n = wid >> 2;
    const int m0 = blockIdx.y * BM;
    const int n0 = blockIdx.x * BN;
    const uint32_t sbase = smem_u32(sm);
    const int NT = K >> 6;

    const int lr = lane & 7, g2 = lane >> 3;

    float acc[2][6][4] = {};

    auto issue = [&](int kt, int s) {
        const char* Ab = (const char*)(A + (size_t)m0 * K + kt * 64);
        uint32_t as = sbase + s * STAGE_BYTES;
#pragma unroll
        for (int i = 0; i < 4; i++) {
            int id = i * 256 + t;
            int row = id >> 3, c = id & 7;
            cp_async16(as + row * 128 + ((c * 16) ^ ((row & 7) << 4)),
                       Ab + (size_t)row * K * 2 + c * 16);
        }
        const char* Bb = (const char*)(W + (size_t)n0 * K + kt * 64);
        uint32_t bs = sbase + s * STAGE_BYTES + A_STAGE;
#pragma unroll
        for (int i = 0; i < 3; i++) {
            int id = i * 256 + t;
            int row = id >> 3, c = id & 7;
            cp_async16(bs + row * 128 + ((c * 16) ^ ((row & 7) << 4)),
                       Bb + (size_t)row * K * 2 + c * 16);
        }
    };

    for (int s = 0; s < 3; s++) {
        if (s < NT) issue(s, s);
        cp_commit();
    }

    for (int kt = 0; kt < NT; kt++) {
        cp_wait<2>();
        __syncthreads();
        int s = kt % 3;
        uint32_t as = sbase + s * STAGE_BYTES;
        uint32_t bs = as + A_STAGE;
#pragma unroll
        for (int ks = 0; ks < 4; ks++) {
            uint32_t a[2][4], b[6][2];
            const int kb = ks * 32;
#pragma unroll
            for (int mf = 0; mf < 2; mf++) {
                int row = warp_m * 32 + mf * 16 + lr + (g2 & 1) * 8;
                int col = kb + (g2 >> 1) * 16;
                ldsm4(a[mf][0], a[mf][1], a[mf][2], a[mf][3],
                      as + row * 128 + (col ^ ((row & 7) << 4)));
            }
#pragma unroll
            for (int p = 0; p < 3; p++) {
                int row = warp_n * 48 + p * 16 + lr + (g2 >> 1) * 8;
                int col = kb + (g2 & 1) * 16;
                uint32_t r0, r1, r2, r3;
                ldsm4(r0, r1, r2, r3, bs + row * 128 + (col ^ ((row & 7) << 4)));
                b[p * 2][0] = r0;     b[p * 2][1] = r1;
                b[p * 2 + 1][0] = r2; b[p * 2 + 1][1] = r3;
            }
#pragma unroll
            for (int mf = 0; mf < 2; mf++)
#pragma unroll
                for (int nf = 0; nf < 6; nf++)
                    mma_bf16(acc[mf][nf], a[mf], b[nf]);
        }
        __syncthreads();
        if (kt + 3 < NT) issue(kt + 3, s);
        cp_commit();
    }

    const int gq = lane >> 2, qq = lane & 3;
#pragma unroll
    for (int mf = 0; mf < 2; mf++) {
#pragma unroll
        for (int nf = 0; nf < 6; nf++) {
#pragma unroll
            for (int half = 0; half < 2; half++) {
                int r = m0 + warp_m * 32 + mf * 16 + gq + half * 8;
                int c = n0 + warp_n * 48 + nf * 8 + 2 * qq;
                float v0 = acc[mf][nf][2 * half + 0] + bias[c];
                float v1 = acc[mf][nf][2 * half + 1] + bias[c + 1];
                if (EPI == 0) {
                    int which = c / DIM;
                    int c2 = c - which * DIM;
                    int hd = c2 >> 5, dd = c2 & 31;
                    int w = r / NWIN, n = r - w * NWIN;
                    size_t off = ((size_t)(w * HEADS + hd) * NWIN + n) * HEADDIM + dd;
                    bf16* dst = (which == 0) ? (bf16*)O0 : (which == 1) ? (bf16*)O1 : (bf16*)O2;
                    if (which == 0) { v0 *= 0.17677669529663687f; v1 *= 0.17677669529663687f; }
                    *(__nv_bfloat162*)(dst + off) = __floats2bfloat162_rn(v0, v1);
                } else if (EPI == 1) {
                    int w = r / NWIN, n = r - w * NWIN;
                    int b = w >> 8, ws = w & 255;
                    int wh = ws >> 4, wc = ws & 15;
                    int ii = n / SS, jj = n - ii * SS;
                    int rr = wh * SS + ii + DD; if (rr >= HH) rr -= HH;
                    int cc = wc * SS + jj + DD; if (cc >= WW) cc -= WW;
                    size_t dst = ((size_t)b * LPIX + rr * WW + cc) * DIM + c;
                    float* o = (float*)O0;
                    o[dst] = v0 + RES[dst];
                    o[dst + 1] = v1 + RES[dst + 1];
                } else if (EPI == 2) {
                    size_t idx = (size_t)r * N + c;
                    float g0 = 0.5f * v0 * (1.0f + erff(v0 * 0.70710678118654752f));
                    float g1 = 0.5f * v1 * (1.0f + erff(v1 * 0.70710678118654752f));
                    *(__nv_bfloat162*)((bf16*)O0 + idx) = __floats2bfloat162_rn(g0, g1);
                } else {
                    size_t idx = (size_t)r * N + c;
                    float* o = (float*)O0;
                    o[idx] = v0 + RES[idx];
                    o[idx + 1] = v1 + RES[idx + 1];
                }
            }
        }
    }
}

// ---------------- attention via mma: one block per (window, head) ----------
#define AST 40
__global__ void __launch_bounds__(128)
attn_kernel(const bf16* __restrict__ q, const bf16* __restrict__ k,
            const bf16* __restrict__ v, const float* __restrict__ rpe,
            bf16* __restrict__ out) {
    int bh = blockIdx.x;
    int w = bh / HEADS, h = bh - w * HEADS;

    __shared__ bf16 qs[64 * AST];
    __shared__ bf16 ks[64 * AST];
    __shared__ bf16 vs[64 * AST];
    __shared__ int lbl[NWIN];

    const int t = threadIdx.x;
    const int wm = t >> 5, lane = t & 31;

    {
        const uint4* qg = (const uint4*)(q + (size_t)bh * NWIN * HEADDIM);
        const uint4* kg = (const uint4*)(k + (size_t)bh * NWIN * HEADDIM);
        const uint4* vg = (const uint4*)(v + (size_t)bh * NWIN * HEADDIM);
        const uint4 zz = make_uint4(0, 0, 0, 0);
#pragma unroll
        for (int it = 0; it < 2; it++) {
            int task = it * 128 + t;
            int row = task >> 2, seg = task & 3;
            bool ok = row < NWIN;
            *(uint4*)&qs[row * AST + seg * 8] = ok ? qg[row * 4 + seg] : zz;
            *(uint4*)&ks[row * AST + seg * 8] = ok ? kg[row * 4 + seg] : zz;
            *(uint4*)&vs[row * AST + seg * 8] = ok ? vg[row * 4 + seg] : zz;
        }
    }
    if (t < NWIN) {
        int ws = w & 255;
        int wh = ws >> 4, wc = ws & 15;
        int ii = t / SS, jj = t - ii * SS;
        int r = wh * SS + ii, c = wc * SS + jj;
        int rb = r < (HH - SS) ? 0 : (r < (HH - DD) ? 1 : 2);
        int cb = c < (WW - SS) ? 0 : (c < (WW - DD) ? 1 : 2);
        const int LT[9] = {0, 5, 4, 7, 8, 6, 2, 3, 1};
        lbl[t] = LT[rb * 3 + cb];
    }
    __syncthreads();

    const uint32_t sq = smem_u32(qs), sk = smem_u32(ks), sv = smem_u32(vs);
    const int sub = lane >> 3, l7 = lane & 7;

    float c[7][4] = {};
#pragma unroll
    for (int kc = 0; kc < 2; kc++) {
        uint32_t a[4];
        {
            int row = wm * 16 + (sub & 1) * 8 + l7;
            int col = kc * 32 + (sub >> 1) * 16;
            ldsm4(a[0], a[1], a[2], a[3], sq + row * (AST * 2) + col);
        }
#pragma unroll
        for (int p = 0; p < 4; p++) {
            int n = p * 16 + (sub >> 1) * 8 + l7;
            int col = kc * 32 + (sub & 1) * 16;
            uint32_t r0, r1, r2, r3;
            ldsm4(r0, r1, r2, r3, sk + n * (AST * 2) + col);
            uint32_t b0[2] = {r0, r1};
            mma_bf16(c[2 * p], a, b0);
            if (p < 3) {
                uint32_t b1[2] = {r2, r3};
                mma_bf16(c[2 * p + 1], a, b1);
            }
        }
    }

    const int g = lane >> 2, qd = lane & 3;
    const int row0 = wm * 16 + g, row1 = row0 + 8;
    const int rr0 = row0 < NWIN ? row0 : 0;
    const int rr1 = row1 < NWIN ? row1 : 0;
    const int l0 = lbl[rr0], l1 = lbl[rr1];
    const int r0i = rr0 / SS, r0j = rr0 - r0i * SS;
    const int r1i = rr1 / SS, r1j = rr1 - r1i * SS;
#pragma unroll
    for (int tt = 0; tt < 7; tt++) {
#pragma unroll
        for (int e = 0; e < 4; e++) {
            int col = tt * 8 + 2 * qd + (e & 1);
            if (col < NWIN) {
                int ci = col / SS, cj = col - ci * SS;
                int ri = (e < 2) ? r0i : r1i, rj = (e < 2) ? r0j : r1j;
                int ll = (e < 2) ? l0 : l1;
                float add = rpe[((ri - ci + 6) * 13 + (rj - cj + 6)) * HEADS + h];
                if (ll != lbl[col]) add -= 100.0f;
                c[tt][e] += add;
            } else {
                c[tt][e] = -1e30f;
            }
        }
    }
    {
        float mx = -1e30f;
#pragma unroll
        for (int tt = 0; tt < 7; tt++) mx = fmaxf(mx, fmaxf(c[tt][0], c[tt][1]));
        mx = fmaxf(mx, __shfl_xor_sync(0xffffffffu, mx, 1));
        mx = fmaxf(mx, __shfl_xor_sync(0xffffffffu, mx, 2));
        float sum = 0.f;
#pragma unroll
        for (int tt = 0; tt < 7; tt++) {
            c[tt][0] = __expf(c[tt][0] - mx); sum += c[tt][0];
            c[tt][1] = __expf(c[tt][1] - mx); sum += c[tt][1];
        }
        sum += __shfl_xor_sync(0xffffffffu, sum, 1);
        sum += __shfl_xor_sync(0xffffffffu, sum, 2);
        float inv = 1.0f / sum;
#pragma unroll
        for (int tt = 0; tt < 7; tt++) { c[tt][0] *= inv; c[tt][1] *= inv; }
    }
    {
        float mx = -1e30f;
#pragma unroll
        for (int tt = 0; tt < 7; tt++) mx = fmaxf(mx, fmaxf(c[tt][2], c[tt][3]));
        mx = fmaxf(mx, __shfl_xor_sync(0xffffffffu, mx, 1));
        mx = fmaxf(mx, __shfl_xor_sync(0xffffffffu, mx, 2));
        float sum = 0.f;
#pragma unroll
        for (int tt = 0; tt < 7; tt++) {
            c[tt][2] = __expf(c[tt][2] - mx); sum += c[tt][2];
            c[tt][3] = __expf(c[tt][3] - mx); sum += c[tt][3];
        }
        sum += __shfl_xor_sync(0xffffffffu, sum, 1);
        sum += __shfl_xor_sync(0xffffffffu, sum, 2);
        float inv = 1.0f / sum;
#pragma unroll
        for (int tt = 0; tt < 7; tt++) { c[tt][2] *= inv; c[tt][3] *= inv; }
    }

    float o[4][4] = {};
#pragma unroll
    for (int kc = 0; kc < 4; kc++) {
        uint32_t a[4];
        a[0] = packbf(c[2 * kc][0], c[2 * kc][1]);
        a[1] = packbf(c[2 * kc][2], c[2 * kc][3]);
        if (2 * kc + 1 < 7) {
            a[2] = packbf(c[2 * kc + 1][0], c[2 * kc + 1][1]);
            a[3] = packbf(c[2 * kc + 1][2], c[2 * kc + 1][3]);
        } else {
            a[2] = 0; a[3] = 0;
        }
#pragma unroll
        for (int p = 0; p < 2; p++) {
            int row = kc * 16 + (sub & 1) * 8 + l7;
            int col = p * 32 + (sub >> 1) * 16;
            uint32_t r0, r1, r2, r3;
            ldsm4t(r0, r1, r2, r3, sv + row * (AST * 2) + col);
            uint32_t b0[2] = {r0, r1}, b1[2] = {r2, r3};
            mma_bf16(o[2 * p], a, b0);
            mma_bf16(o[2 * p + 1], a, b1);
        }
    }

    bf16* ob = out + (size_t)w * NWIN * DIM + h * HEADDIM;
    if (row0 < NWIN) {
#pragma unroll
        for (int nt = 0; nt < 4; nt++) {
            __nv_bfloat162 pv = __floats2bfloat162_rn(o[nt][0], o[nt][1]);
            *(__nv_bfloat162*)&ob[(size_t)row0 * DIM + nt * 8 + 2 * qd] = pv;
        }
    }
    if (row1 < NWIN) {
#pragma unroll
        for (int nt = 0; nt < 4; nt++) {
            __nv_bfloat162 pv = __floats2bfloat162_rn(o[nt][2], o[nt][3]);
            *(__nv_bfloat162*)&ob[(size_t)row1 * DIM + nt * 8 + 2 * qd] = pv;
        }
    }
}

// ---------------- launcher ----------------
extern "C" void kernel_launch(void* const* d_in, const int* in_sizes, int n_in,
                              void* d_out, int out_size) {
    const float* x      = (const float*)d_in[0];
    const float* w_qkv  = (const float*)d_in[1];
    const float* b_qkv  = (const float*)d_in[2];
    const float* w_proj = (const float*)d_in[3];
    const float* b_proj = (const float*)d_in[4];
    const float* rpe    = (const float*)d_in[5];
    const float* gamma1 = (const float*)d_in[6];
    const float* beta1  = (const float*)d_in[7];
    const float* gamma2 = (const float*)d_in[8];
    const float* beta2  = (const float*)d_in[9];
    const float* w_fc1  = (const float*)d_in[10];
    const float* b_fc1  = (const float*)d_in[11];
    const float* w_fc2  = (const float*)d_in[12];
    const float* b_fc2  = (const float*)d_in[13];
    float* out = (float*)d_out;

    bf16 *win, *q, *k, *v, *att, *hbuf, *wqkv, *wproj, *wfc1, *wfc2;
    float* x1;
    cudaGetSymbolAddress((void**)&win,   g_win);
    cudaGetSymbolAddress((void**)&q,     g_q);
    cudaGetSymbolAddress((void**)&k,     g_k);
    cudaGetSymbolAddress((void**)&v,     g_v);
    cudaGetSymbolAddress((void**)&att,   g_att);
    cudaGetSymbolAddress((void**)&x1,    g_x1);
    cudaGetSymbolAddress((void**)&hbuf,  g_h);
    cudaGetSymbolAddress((void**)&wqkv,  g_wqkv);
    cudaGetSymbolAddress((void**)&wproj, g_wproj);
    cudaGetSymbolAddress((void**)&wfc1,  g_wfc1);
    cudaGetSymbolAddress((void**)&wfc2,  g_wfc2);

    cudaFuncSetAttribute(gemm_bf16<0>, cudaFuncAttributeMaxDynamicSharedMemorySize, GEMM_SMEM);
    cudaFuncSetAttribute(gemm_bf16<1>, cudaFuncAttributeMaxDynamicSharedMemorySize, GEMM_SMEM);
    cudaFuncSetAttribute(gemm_bf16<2>, cudaFuncAttributeMaxDynamicSharedMemorySize, GEMM_SMEM);
    cudaFuncSetAttribute(gemm_bf16<3>, cudaFuncAttributeMaxDynamicSharedMemorySize, GEMM_SMEM);

    // 0) all weight conversions in one launch
    cvt_all<<<(N4_ALL + 255) / 256, 256>>>(
        (const float4*)w_qkv, (const float4*)w_proj, (const float4*)w_fc1,
        (const float4*)w_fc2, (__nv_bfloat162*)wqkv, (__nv_bfloat162*)wproj,
        (__nv_bfloat162*)wfc1, (__nv_bfloat162*)wfc2);

    const int LN_BLOCKS = TOKENS / 8;
    const int MT = TOKENS / BM;   // 1568

    // 1) LN1 + shift + window gather
    ln_kernel<true><<<LN_BLOCKS, 256>>>(x, gamma1, beta1, win);

    // 2) QKV GEMM (N=576)
    gemm_bf16<0><<<dim3(576 / BN, MT), 256, GEMM_SMEM>>>(
        win, wqkv, b_qkv, q, k, v, nullptr, TOKENS, 3 * DIM, DIM);

    // 3) windowed attention (mma)
    attn_kernel<<<BW * HEADS, 128>>>(q, k, v, rpe, att);

    // 4) proj GEMM + unshift + residual -> x1 (fp32)
    gemm_bf16<1><<<dim3(DIM / BN, MT), 256, GEMM_SMEM>>>(
        att, wproj, b_proj, x1, nullptr, nullptr, x, TOKENS, DIM, DIM);

    // 5) LN2 -> bf16
    ln_kernel<false><<<LN_BLOCKS, 256>>>(x1, gamma2, beta2, win);

    // 6) fc1 GEMM + GELU (N=768) -> bf16
    gemm_bf16<2><<<dim3(HIDDEN / BN, MT), 256, GEMM_SMEM>>>(
        win, wfc1, b_fc1, hbuf, nullptr, nullptr, nullptr, TOKENS, HIDDEN, DIM);

    // 7) fc2 GEMM + residual(x1) -> fp32 d_out (K=768)
    gemm_bf16<3><<<dim3(DIM / BN, MT), 256, GEMM_SMEM>>>(
        hbuf, wfc2, b_fc2, out, nullptr, nullptr, x1, TOKENS, DIM, HIDDEN);
}